// round 14
// baseline (speedup 1.0000x reference)
#include <cuda_runtime.h>
#include <cuda_bf16.h>
#include <cstdint>

#define TSTRIDE 32768
#define THREADS 512

// smem byte offsets
#define BUF0 0u
#define BUF1 65536u
#define BUF2 131072u
#define WOFF 196608u
#define SCOFF 229376u     // SCA: 512 floats (128 rows x 4 quadrants)
#define SMEM_TOT 231424

// Weight images: [wk, wq, wv, wo, w1, w2], each = [hi 32KB | lo 32KB]
__device__ __align__(16) unsigned char g_w[6][65536];

#define SWC(c, r7) ((uint32_t)(((((c) ^ (r7)) & 7) | ((c) & 8)) << 4))

// S-tile assignment (per-warp (sm,sn) bijection, balanced across SMSPs)
#define SMTAB 0x1000212133213320ull
#define SNTAB 0x3321322131102000ull

__device__ __forceinline__ uint32_t smem_u32(const void* p) {
    uint32_t a;
    asm("{ .reg .u64 t; cvta.to.shared.u64 t, %1; cvt.u32.u64 %0, t; }" : "=r"(a) : "l"(p));
    return a;
}
__device__ __forceinline__ uint32_t f2bf2(float a, float b) {   // lo=a, hi=b
    uint32_t r;
    asm("cvt.rn.bf16x2.f32 %0, %1, %2;" : "=r"(r) : "f"(b), "f"(a));
    return r;
}
__device__ __forceinline__ float2 bf2f2(uint32_t u) {
    __nv_bfloat162 h = *reinterpret_cast<__nv_bfloat162*>(&u);
    return __bfloat1622float2(h);
}
__device__ __forceinline__ void ldsm4(uint32_t* r, uint32_t a) {
    asm volatile("ldmatrix.sync.aligned.m8n8.x4.shared.b16 {%0,%1,%2,%3}, [%4];"
        : "=r"(r[0]), "=r"(r[1]), "=r"(r[2]), "=r"(r[3]) : "r"(a));
}
__device__ __forceinline__ void mma_bf16(float* d, const uint32_t* a, uint32_t b0, uint32_t b1) {
    asm volatile("mma.sync.aligned.m16n8k16.row.col.f32.bf16.bf16.f32 "
        "{%0,%1,%2,%3}, {%4,%5,%6,%7}, {%8,%9}, {%0,%1,%2,%3};"
        : "+f"(d[0]), "+f"(d[1]), "+f"(d[2]), "+f"(d[3])
        : "r"(a[0]), "r"(a[1]), "r"(a[2]), "r"(a[3]), "r"(b0), "r"(b1));
}
#define STS32(a, v)  asm volatile("st.shared.b32 [%0], %1;" :: "r"(a), "r"(v) : "memory")
#define STS128(a, v0, v1, v2, v3) \
    asm volatile("st.shared.v4.b32 [%0], {%1,%2,%3,%4};" \
        :: "r"(a), "r"(v0), "r"(v1), "r"(v2), "r"(v3) : "memory")
#define LDS32(v, a)  asm volatile("ld.shared.b32 %0, [%1];" : "=r"(v) : "r"(a))
#define STSF(a, v)   asm volatile("st.shared.f32 [%0], %1;" :: "r"(a), "f"(v) : "memory")
#define LDSF(v, a)   asm volatile("ld.shared.f32 %0, [%1];" : "=f"(v) : "r"(a))
#define CP16(d, s) \
    asm volatile("cp.async.cg.shared.global [%0], [%1], 16;" :: "r"(d), "l"(s) : "memory")
#define CP_COMMIT  asm volatile("cp.async.commit_group;" ::: "memory")
#define CP_WAITALL asm volatile("cp.async.wait_group 0;" ::: "memory")
#define QRED(v) do { v += __shfl_xor_sync(~0u, v, 1); v += __shfl_xor_sync(~0u, v, 2); } while (0)

// ============ prep kernel ============
__global__ void prep_w(const float* __restrict__ wk, const float* __restrict__ wq,
                       const float* __restrict__ wv, const float* __restrict__ wo,
                       const float* __restrict__ w1, const float* __restrict__ w2) {
    const float* ws[6] = {wk, wq, wv, wo, w1, w2};
    const float* src = ws[blockIdx.x];
    unsigned char* dst = g_w[blockIdx.x];
    for (int e = threadIdx.x; e < 16384; e += blockDim.x) {
        int f = e >> 7, k = e & 127;
        float val = src[k * 128 + f];            // W^T[f][k]
        __nv_bfloat16 h = __float2bfloat16(val);
        __nv_bfloat16 l = __float2bfloat16(val - __bfloat162float(h));
        uint32_t off = (uint32_t)f * 256 + SWC(k >> 3, f & 7) + (uint32_t)(k & 7) * 2;
        *(__nv_bfloat16*)(dst + off) = h;
        *(__nv_bfloat16*)(dst + 32768 + off) = l;
    }
}

// ============ cp.async staging ============
__device__ __forceinline__ void cpa32(uint32_t dst, const unsigned char* src, int tid) {
#pragma unroll
    for (int i = 0; i < 4; i++)
        CP16(dst + (uint32_t)(tid * 16 + i * 8192), src + tid * 16 + i * 8192);
}
__device__ __forceinline__ void cpa64(uint32_t dst, const unsigned char* src, int tid) {
#pragma unroll
    for (int i = 0; i < 8; i++)
        CP16(dst + (uint32_t)(tid * 16 + i * 8192), src + tid * 16 + i * 8192);
}

// ============ GEMM core: 32x32 warp tile, round-robin mma order ============
__device__ __forceinline__ void gchunk(uint32_t ahb, uint32_t alb, uint32_t bhb,
                                       uint32_t blb, float* acc,
                                       uint32_t ar0, uint32_t ar1,
                                       uint32_t br0, uint32_t br1, uint32_t csw) {
    uint32_t a0h[4], a0l[4], a1h[4], a1l[4];
    uint32_t b0h[4], b0l[4], b1h[4], b1l[4];
    ldsm4(a0h, ahb + ar0 + csw);
    ldsm4(a1h, ahb + ar1 + csw);
    ldsm4(b0h, bhb + br0 + csw);
    ldsm4(b1h, bhb + br1 + csw);
    ldsm4(a0l, alb + ar0 + csw);
    ldsm4(a1l, alb + ar1 + csw);
    ldsm4(b0l, blb + br0 + csw);
    ldsm4(b1l, blb + br1 + csw);
    mma_bf16(acc+0,  a0h, b0h[0], b0h[2]); mma_bf16(acc+4,  a0h, b0h[1], b0h[3]);
    mma_bf16(acc+8,  a0h, b1h[0], b1h[2]); mma_bf16(acc+12, a0h, b1h[1], b1h[3]);
    mma_bf16(acc+16, a1h, b0h[0], b0h[2]); mma_bf16(acc+20, a1h, b0h[1], b0h[3]);
    mma_bf16(acc+24, a1h, b1h[0], b1h[2]); mma_bf16(acc+28, a1h, b1h[1], b1h[3]);
    mma_bf16(acc+0,  a0l, b0h[0], b0h[2]); mma_bf16(acc+4,  a0l, b0h[1], b0h[3]);
    mma_bf16(acc+8,  a0l, b1h[0], b1h[2]); mma_bf16(acc+12, a0l, b1h[1], b1h[3]);
    mma_bf16(acc+16, a1l, b0h[0], b0h[2]); mma_bf16(acc+20, a1l, b0h[1], b0h[3]);
    mma_bf16(acc+24, a1l, b1h[0], b1h[2]); mma_bf16(acc+28, a1l, b1h[1], b1h[3]);
    mma_bf16(acc+0,  a0h, b0l[0], b0l[2]); mma_bf16(acc+4,  a0h, b0l[1], b0l[3]);
    mma_bf16(acc+8,  a0h, b1l[0], b1l[2]); mma_bf16(acc+12, a0h, b1l[1], b1l[3]);
    mma_bf16(acc+16, a1h, b0l[0], b0l[2]); mma_bf16(acc+20, a1h, b0l[1], b0l[3]);
    mma_bf16(acc+24, a1h, b1l[0], b1l[2]); mma_bf16(acc+28, a1h, b1l[1], b1l[3]);
}

__device__ __forceinline__ void gfull(uint32_t ahb, uint32_t alb, uint32_t bhb,
                                      uint32_t blb, float* acc, int m0, int cb,
                                      int noff, int khalf) {
    const int rr = noff & 7;
    const uint32_t ar0 = (uint32_t)((m0 + noff) * 256), ar1 = ar0 + 4096;
    const uint32_t br0 = (uint32_t)((cb + noff) * 256), br1 = br0 + 4096;
#pragma unroll
    for (int j = 0; j < 8; j++)
        gchunk(ahb, alb, bhb, blb, acc, ar0, ar1, br0, br1, SWC(2 * j + khalf, rr));
}
__device__ __forceinline__ void gvar(uint32_t ahb, uint32_t alb, uint32_t bhb,
                                     uint32_t blb, float* acc, int m0, int cb,
                                     int noff, int khalf, int jmax) {
    const int rr = noff & 7;
    const uint32_t ar0 = (uint32_t)((m0 + noff) * 256), ar1 = ar0 + 4096;
    const uint32_t br0 = (uint32_t)((cb + noff) * 256), br1 = br0 + 4096;
#pragma unroll 2
    for (int j = 0; j < jmax; j++)
        gchunk(ahb, alb, bhb, blb, acc, ar0, ar1, br0, br1, SWC(2 * j + khalf, rr));
}
// acc += (Ah+Al) @ B (single B half), round-robin
__device__ __forceinline__ void gAB(uint32_t ahb, uint32_t alb, uint32_t bb,
                                    float* acc, int m0, int cb, int noff, int khalf) {
    const int rr = noff & 7;
    const uint32_t ar0 = (uint32_t)((m0 + noff) * 256), ar1 = ar0 + 4096;
    const uint32_t br0 = (uint32_t)((cb + noff) * 256), br1 = br0 + 4096;
#pragma unroll
    for (int j = 0; j < 8; j++) {
        const uint32_t csw = SWC(2 * j + khalf, rr);
        uint32_t a0h[4], a0l[4], a1h[4], a1l[4], b0[4], b1[4];
        ldsm4(a0h, ahb + ar0 + csw); ldsm4(a1h, ahb + ar1 + csw);
        ldsm4(b0, bb + br0 + csw);   ldsm4(b1, bb + br1 + csw);
        ldsm4(a0l, alb + ar0 + csw); ldsm4(a1l, alb + ar1 + csw);
        mma_bf16(acc+0,  a0h, b0[0], b0[2]); mma_bf16(acc+4,  a0h, b0[1], b0[3]);
        mma_bf16(acc+8,  a0h, b1[0], b1[2]); mma_bf16(acc+12, a0h, b1[1], b1[3]);
        mma_bf16(acc+16, a1h, b0[0], b0[2]); mma_bf16(acc+20, a1h, b0[1], b0[3]);
        mma_bf16(acc+24, a1h, b1[0], b1[2]); mma_bf16(acc+28, a1h, b1[1], b1[3]);
        mma_bf16(acc+0,  a0l, b0[0], b0[2]); mma_bf16(acc+4,  a0l, b0[1], b0[3]);
        mma_bf16(acc+8,  a0l, b1[0], b1[2]); mma_bf16(acc+12, a0l, b1[1], b1[3]);
        mma_bf16(acc+16, a1l, b0[0], b0[2]); mma_bf16(acc+20, a1l, b0[1], b0[3]);
        mma_bf16(acc+24, a1l, b1[0], b1[2]); mma_bf16(acc+28, a1l, b1[1], b1[3]);
    }
}
// acc += A @ B (single A, single B half)
__device__ __forceinline__ void gA(uint32_t ab, uint32_t bb, float* acc,
                                   int m0, int cb, int noff, int khalf) {
    const int rr = noff & 7;
    const uint32_t ar0 = (uint32_t)((m0 + noff) * 256), ar1 = ar0 + 4096;
    const uint32_t br0 = (uint32_t)((cb + noff) * 256), br1 = br0 + 4096;
#pragma unroll
    for (int j = 0; j < 8; j++) {
        const uint32_t csw = SWC(2 * j + khalf, rr);
        uint32_t a0[4], a1[4], b0[4], b1[4];
        ldsm4(a0, ab + ar0 + csw); ldsm4(a1, ab + ar1 + csw);
        ldsm4(b0, bb + br0 + csw); ldsm4(b1, bb + br1 + csw);
        mma_bf16(acc+0,  a0, b0[0], b0[2]); mma_bf16(acc+4,  a0, b0[1], b0[3]);
        mma_bf16(acc+8,  a0, b1[0], b1[2]); mma_bf16(acc+12, a0, b1[1], b1[3]);
        mma_bf16(acc+16, a1, b0[0], b0[2]); mma_bf16(acc+20, a1, b0[1], b0[3]);
        mma_bf16(acc+24, a1, b1[0], b1[2]); mma_bf16(acc+28, a1, b1[1], b1[3]);
    }
}

__device__ __forceinline__ void zacc(float* acc) {
#pragma unroll
    for (int i = 0; i < 32; i++) acc[i] = 0.0f;
}

// store acc (rows m0+16rs+g, +8; cols cb..cb+32) as hi/lo bf16 image
__device__ __forceinline__ void simg(uint32_t ibase, const float* acc, int m0, int cb,
                                     int g, int q) {
#pragma unroll
    for (int rs = 0; rs < 2; rs++)
#pragma unroll
        for (int tn = 0; tn < 2; tn++) {
            const float* e = acc + rs * 16 + tn * 8;
            int row = m0 + 16 * rs + g;
            uint32_t a0 = ibase + (uint32_t)(row * 256) + SWC((cb >> 3) + 2 * tn, g) + 4 * q;
            uint32_t a1 = ibase + (uint32_t)(row * 256) + SWC((cb >> 3) + 2 * tn + 1, g) + 4 * q;
            uint32_t h0 = f2bf2(e[0], e[1]), h1 = f2bf2(e[2], e[3]);
            float2 f0 = bf2f2(h0), f1 = bf2f2(h1);
            uint32_t l0 = f2bf2(e[0] - f0.x, e[1] - f0.y);
            uint32_t l1 = f2bf2(e[2] - f1.x, e[3] - f1.y);
            STS32(a0, h0);        STS32(a0 + 32768, l0);
            STS32(a0 + 2048, h1); STS32(a0 + 2048 + 32768, l1);
            uint32_t h2 = f2bf2(e[4], e[5]), h3 = f2bf2(e[6], e[7]);
            float2 f2 = bf2f2(h2), f3 = bf2f2(h3);
            uint32_t l2 = f2bf2(e[4] - f2.x, e[5] - f2.y);
            uint32_t l3 = f2bf2(e[6] - f3.x, e[7] - f3.y);
            STS32(a1, h2);        STS32(a1 + 32768, l2);
            STS32(a1 + 2048, h3); STS32(a1 + 2048 + 32768, l3);
        }
}

__device__ __forceinline__ void biasc(float* acc, const float* __restrict__ bias,
                                      int cb, int q) {
#pragma unroll
    for (int rs = 0; rs < 2; rs++)
#pragma unroll
        for (int tn = 0; tn < 2; tn++) {
            float* e = acc + rs * 16 + tn * 8;
            float2 b0 = __ldg((const float2*)(bias + cb + 16 * tn + 2 * q));
            float2 b1 = __ldg((const float2*)(bias + cb + 16 * tn + 8 + 2 * q));
            e[0] += b0.x; e[1] += b0.y; e[2] += b0.x; e[3] += b0.y;
            e[4] += b1.x; e[5] += b1.y; e[6] += b1.x; e[7] += b1.y;
        }
}

// ============ main kernel ============
__global__ void __launch_bounds__(THREADS, 1)
fused_hmma9(const float* __restrict__ x, const float* __restrict__ te,
            const float* __restrict__ bq, const float* __restrict__ bk,
            const float* __restrict__ bv, const float* __restrict__ bo,
            const float* __restrict__ b1, const float* __restrict__ b2,
            float* __restrict__ out) {
    extern __shared__ char smc[];
    const uint32_t sb = smem_u32(smc);
    const uint32_t B0 = sb + BUF0, B1 = sb + BUF1, B2 = sb + BUF2, W = sb + WOFF;
    const uint32_t SCA = sb + SCOFF;
    const uint32_t WS = W;                // LN sumsq scratch (W dead at LN time)

    const int tid = threadIdx.x, lane = tid & 31, w = tid >> 5;
    const int wm = w >> 2, wn = w & 3;
    const int m0 = 32 * wm, cb = 32 * wn;
    const int g = lane >> 2, q = lane & 3;
    const int noff = ((lane >> 3) & 1) * 8 + (lane & 7);
    const int khalf = lane >> 4;
    const int rA = m0 + g;                // rows rA, +8, +16, +24

    const int bn = blockIdx.x, b = bn >> 8, n = bn & 255;
    const float* xb  = x  + (size_t)b * 128 * TSTRIDE + (size_t)n * 128;
    const float* teb = te + (size_t)b * 128 * TSTRIDE + (size_t)n * 128;
    float* ob = out + (size_t)b * 128 * TSTRIDE + (size_t)n * 128;

    // G0: prefetch Wk -> BUF2, Wv -> BUF1, Wq-hi -> W
    cpa64(B2, g_w[0], tid);
    cpa64(B1, g_w[2], tid);
    cpa32(W, g_w[1], tid);
    CP_COMMIT;

    // ---- build X = x+te hi/lo image -> BUF0 ----
    {
        int row = tid >> 2, quarter = tid & 3;
        const float4* xr = (const float4*)(xb  + (size_t)row * TSTRIDE + 32 * quarter);
        const float4* tr = (const float4*)(teb + (size_t)row * TSTRIDE + 32 * quarter);
#pragma unroll
        for (int ci = 0; ci < 4; ci++) {
            float4 a = xr[2*ci], c = tr[2*ci], a2 = xr[2*ci+1], c2 = tr[2*ci+1];
            float v0 = a.x + c.x, v1 = a.y + c.y, v2 = a.z + c.z, v3 = a.w + c.w;
            float v4 = a2.x + c2.x, v5 = a2.y + c2.y, v6 = a2.z + c2.z, v7 = a2.w + c2.w;
            uint32_t h0 = f2bf2(v0, v1), h1 = f2bf2(v2, v3);
            uint32_t h2 = f2bf2(v4, v5), h3 = f2bf2(v6, v7);
            float2 e0 = bf2f2(h0), e1 = bf2f2(h1), e2 = bf2f2(h2), e3 = bf2f2(h3);
            uint32_t l0 = f2bf2(v0 - e0.x, v1 - e0.y), l1 = f2bf2(v2 - e1.x, v3 - e1.y);
            uint32_t l2 = f2bf2(v4 - e2.x, v5 - e2.y), l3 = f2bf2(v6 - e3.x, v7 - e3.y);
            uint32_t addr = B0 + (uint32_t)row * 256 + SWC(4 * quarter + ci, row & 7);
            STS128(addr, h0, h1, h2, h3);
            STS128(addr + 32768, l0, l1, l2, l3);
        }
    }
    CP_WAITALL;
    __syncthreads();

    float acc[32];

    // ==== Phase 1+2 merged: K = X @ Wk and V^T = Wv^T @ X (dual acc) ====
    {
        float acc2[32];
        zacc(acc); zacc(acc2);
        const int rr = noff & 7;
        const uint32_t ar0 = (uint32_t)((m0 + noff) * 256), ar1 = ar0 + 4096;
        const uint32_t br0 = (uint32_t)((cb + noff) * 256), br1 = br0 + 4096;
#pragma unroll
        for (int j = 0; j < 8; j++) {
            const uint32_t csw = SWC(2 * j + khalf, rr);
            // K: A = X (B0), B = Wk (B2)
            gchunk(B0, B0 + 32768, B2, B2 + 32768, acc, ar0, ar1, br0, br1, csw);
            // V^T: A = Wv (B1), B = X (B0)
            gchunk(B1, B1 + 32768, B0, B0 + 32768, acc2, ar0, ar1, br0, br1, csw);
        }
        biasc(acc, bk, cb, q);
        {
            float bv0 = __ldg(bv + rA), bv1 = __ldg(bv + rA + 8);
            float bv2 = __ldg(bv + rA + 16), bv3 = __ldg(bv + rA + 24);
#pragma unroll
            for (int tn = 0; tn < 2; tn++) {
#pragma unroll
                for (int j = 0; j < 4; j++) {
                    acc2[8*tn + j] += (j < 2) ? bv0 : bv1;
                    acc2[8*tn + 4 + j] += (j < 2) ? bv0 : bv1;
                    acc2[16 + 8*tn + j] += (j < 2) ? bv2 : bv3;
                    acc2[16 + 8*tn + 4 + j] += (j < 2) ? bv2 : bv3;
                }
            }
        }
        __syncthreads();               // all reads of B0/B1/B2 in merged phase done
        simg(B2, acc, m0, cb, g, q);   // K image (overwrites Wk)
        simg(B1, acc2, m0, cb, g, q);  // V^T image (overwrites Wv)
    }

    // ==== Phase 3: Q = X @ Wq -> BUF0 (W-lo prefetched in registers) ====
    {
        uint4 p[4];
        {
            const uint4* s = (const uint4*)(g_w[1] + 32768);
#pragma unroll
            for (int i = 0; i < 4; i++) p[i] = s[tid + 512 * i];
        }
        zacc(acc);
        gAB(B0, B0 + 32768, W, acc, m0, cb, noff, khalf);  // (Xh+Xl)@Wqh
        __syncthreads();                                   // Wq-hi reads + simg K/V done
        {
            uint4* d = (uint4*)(smc + WOFF);
#pragma unroll
            for (int i = 0; i < 4; i++) d[tid + 512 * i] = p[i];
        }
        __syncthreads();                                   // Wq-lo visible
        gA(B0, W, acc, m0, cb, noff, khalf);               // Xh@Wql
        biasc(acc, bq, cb, q);
        __syncthreads();                                   // X + Wq-lo reads done
        cpa32(W, g_w[3], tid); CP_COMMIT;                  // G2: Wo-hi -> W
        simg(B0, acc, m0, cb, g, q);                       // Q image
        __syncthreads();
    }

    // ==== Phase 4: S (assigned tile) -> causal softmax -> P -> BUF0 ====
    {
        const int sm = (int)((SMTAB >> (4 * w)) & 7);
        const int sn = (int)((SNTAB >> (4 * w)) & 7);
        const bool masked = sn > sm;
        const int sm0 = 32 * sm, scb = 32 * sn;
        const int rS = sm0 + g;
        zacc(acc);
        if (!masked)
            gfull(B0, B0 + 32768, B2, B2 + 32768, acc, sm0, scb, noff, khalf);
        float s[4] = {0, 0, 0, 0};
        if (!masked) {
#pragma unroll
            for (int rs = 0; rs < 2; rs++)
#pragma unroll
                for (int tn = 0; tn < 2; tn++) {
                    float* e = acc + rs * 16 + tn * 8;
                    int ra = rS + 16 * rs, rb = ra + 8;
                    int c0 = scb + 16 * tn + 2 * q;
                    int c1 = c0 + 8;
                    float p0 = (c0     <= ra) ? __expf(e[0] * 0.25f) : 0.0f;
                    float p1 = (c0 + 1 <= ra) ? __expf(e[1] * 0.25f) : 0.0f;
                    float p2 = (c0     <= rb) ? __expf(e[2] * 0.25f) : 0.0f;
                    float p3 = (c0 + 1 <= rb) ? __expf(e[3] * 0.25f) : 0.0f;
                    float p4 = (c1     <= ra) ? __expf(e[4] * 0.25f) : 0.0f;
                    float p5 = (c1 + 1 <= ra) ? __expf(e[5] * 0.25f) : 0.0f;
                    float p6 = (c1     <= rb) ? __expf(e[6] * 0.25f) : 0.0f;
                    float p7 = (c1 + 1 <= rb) ? __expf(e[7] * 0.25f) : 0.0f;
                    e[0]=p0; e[1]=p1; e[2]=p2; e[3]=p3; e[4]=p4; e[5]=p5; e[6]=p6; e[7]=p7;
                    s[2*rs]   += p0 + p1 + p4 + p5;
                    s[2*rs+1] += p2 + p3 + p6 + p7;
                }
        }
        QRED(s[0]); QRED(s[1]); QRED(s[2]); QRED(s[3]);
        STSF(SCA + (uint32_t)(4 * rS + sn) * 4, s[0]);
        STSF(SCA + (uint32_t)(4 * (rS + 8) + sn) * 4, s[1]);
        STSF(SCA + (uint32_t)(4 * (rS + 16) + sn) * 4, s[2]);
        STSF(SCA + (uint32_t)(4 * (rS + 24) + sn) * 4, s[3]);
        __syncthreads();                                   // K,Q reads + sums ALL done
        cpa32(B2 + 32768, g_w[3] + 32768, tid); CP_COMMIT; // G3: Wo-lo -> B2lo (K now dead)
        if (!masked) {
            float inv[4];
#pragma unroll
            for (int i = 0; i < 4; i++) {
                float a0, a1, a2, a3;
                uint32_t base = SCA + (uint32_t)(4 * (rS + 8 * i)) * 4;
                LDSF(a0, base); LDSF(a1, base + 4); LDSF(a2, base + 8); LDSF(a3, base + 12);
                inv[i] = 1.0f / (a0 + a1 + a2 + a3);
            }
#pragma unroll
            for (int rs = 0; rs < 2; rs++)
#pragma unroll
                for (int tn = 0; tn < 2; tn++) {
                    float* e = acc + rs * 16 + tn * 8;
                    e[0] *= inv[2*rs]; e[1] *= inv[2*rs];
                    e[2] *= inv[2*rs+1]; e[3] *= inv[2*rs+1];
                    e[4] *= inv[2*rs]; e[5] *= inv[2*rs];
                    e[6] *= inv[2*rs+1]; e[7] *= inv[2*rs+1];
                }
            simg(B0, acc, sm0, scb, g, q);                 // P image (lower tiles only)
        }
        __syncthreads();
    }

    // ==== Phase 5: AO = P @ V (k bounded: jmax = 2wm+2) -> BUF0 ====
    zacc(acc);
    gvar(B0, B0 + 32768, B1, B1 + 32768, acc, m0, cb, noff, khalf, 2 * wm + 2);
    __syncthreads();
    simg(B0, acc, m0, cb, g, q);                           // AO image
    CP_WAITALL;
    __syncthreads();
    cpa64(B1, g_w[4], tid); CP_COMMIT;                     // G4: W1 -> BUF1

    // ==== Phase 6: U = LN(AO @ Wo + bo + (x+te)) -> BUF2 ====
    zacc(acc);
    gfull(B0, B0 + 32768, W, B2 + 32768, acc, m0, cb, noff, khalf);
    biasc(acc, bo, cb, q);
#pragma unroll
    for (int rs = 0; rs < 2; rs++)
#pragma unroll
        for (int tn = 0; tn < 2; tn++) {
            float* e = acc + rs * 16 + tn * 8;
            int c = cb + 16 * tn + 2 * q;
            size_t ra = (size_t)(rA + 16 * rs), rb = ra + 8;
            float2 xa = *(const float2*)(xb + ra * TSTRIDE + c);
            float2 ta = *(const float2*)(teb + ra * TSTRIDE + c);
            e[0] += xa.x + ta.x; e[1] += xa.y + ta.y;
            float2 xc = *(const float2*)(xb + rb * TSTRIDE + c);
            float2 tc = *(const float2*)(teb + rb * TSTRIDE + c);
            e[2] += xc.x + tc.x; e[3] += xc.y + tc.y;
            float2 xe = *(const float2*)(xb + ra * TSTRIDE + c + 8);
            float2 tee = *(const float2*)(teb + ra * TSTRIDE + c + 8);
            e[4] += xe.x + tee.x; e[5] += xe.y + tee.y;
            float2 xg = *(const float2*)(xb + rb * TSTRIDE + c + 8);
            float2 tg = *(const float2*)(teb + rb * TSTRIDE + c + 8);
            e[6] += xg.x + tg.x; e[7] += xg.y + tg.y;
        }
    {   // 1-round LN: sum -> SCA, sumsq -> WS
        float s[4] = {0,0,0,0}, qq[4] = {0,0,0,0};
#pragma unroll
        for (int rs = 0; rs < 2; rs++)
#pragma unroll
            for (int tn = 0; tn < 2; tn++) {
                float* e = acc + rs * 16 + tn * 8;
                s[2*rs]   += e[0] + e[1] + e[4] + e[5];
                s[2*rs+1] += e[2] + e[3] + e[6] + e[7];
                qq[2*rs]   += e[0]*e[0] + e[1]*e[1] + e[4]*e[4] + e[5]*e[5];
                qq[2*rs+1] += e[2]*e[2] + e[3]*e[3] + e[6]*e[6] + e[7]*e[7];
            }
        QRED(s[0]); QRED(s[1]); QRED(s[2]); QRED(s[3]);
        QRED(qq[0]); QRED(qq[1]); QRED(qq[2]); QRED(qq[3]);
#pragma unroll
        for (int i = 0; i < 4; i++) {
            STSF(SCA + (uint32_t)(4 * (rA + 8 * i) + wn) * 4, s[i]);
            STSF(WS + (uint32_t)(4 * (rA + 8 * i) + wn) * 4, qq[i]);
        }
        __syncthreads();
        float mu[4], iv[4];
#pragma unroll
        for (int i = 0; i < 4; i++) {
            float a0, a1, a2, a3, c0, c1, c2, c3;
            uint32_t bs = SCA + (uint32_t)(4 * (rA + 8 * i)) * 4;
            uint32_t bw = WS + (uint32_t)(4 * (rA + 8 * i)) * 4;
            LDSF(a0, bs); LDSF(a1, bs + 4); LDSF(a2, bs + 8); LDSF(a3, bs + 12);
            LDSF(c0, bw); LDSF(c1, bw + 4); LDSF(c2, bw + 8); LDSF(c3, bw + 12);
            mu[i] = (a0 + a1 + a2 + a3) * 0.0078125f;
            float var = (c0 + c1 + c2 + c3) * 0.0078125f - mu[i] * mu[i];
            iv[i] = rsqrtf(var + 1e-5f);
        }
#pragma unroll
        for (int rs = 0; rs < 2; rs++)
#pragma unroll
            for (int tn = 0; tn < 2; tn++) {
                float* e = acc + rs * 16 + tn * 8;
                e[0] = (e[0] - mu[2*rs]) * iv[2*rs];   e[1] = (e[1] - mu[2*rs]) * iv[2*rs];
                e[4] = (e[4] - mu[2*rs]) * iv[2*rs];   e[5] = (e[5] - mu[2*rs]) * iv[2*rs];
                e[2] = (e[2] - mu[2*rs+1]) * iv[2*rs+1]; e[3] = (e[3] - mu[2*rs+1]) * iv[2*rs+1];
                e[6] = (e[6] - mu[2*rs+1]) * iv[2*rs+1]; e[7] = (e[7] - mu[2*rs+1]) * iv[2*rs+1];
            }
    }
    __syncthreads();                                       // WS reads done before G5
    cpa32(W, g_w[5], tid); CP_COMMIT;                      // G5: W2-hi -> W
    simg(B2, acc, m0, cb, g, q);                           // U image
    CP_WAITALL;
    __syncthreads();

    // ==== Phase 7: H = relu(U @ W1 + b1) -> BUF0 ====
    zacc(acc);
    gfull(B2, B2 + 32768, B1, B1 + 32768, acc, m0, cb, noff, khalf);
    biasc(acc, b1, cb, q);
#pragma unroll
    for (int i = 0; i < 32; i++) acc[i] = fmaxf(acc[i], 0.0f);
    __syncthreads();
    cpa32(B1 + 32768, g_w[5] + 32768, tid); CP_COMMIT;     // G6: W2-lo -> BUF1lo
    simg(B0, acc, m0, cb, g, q);                           // H image
    CP_WAITALL;
    __syncthreads();

    // ==== Phase 8: out = LN(H @ W2 + b2 + U) -> gmem ====
    zacc(acc);
    gfull(B0, B0 + 32768, W, B1 + 32768, acc, m0, cb, noff, khalf);
    biasc(acc, b2, cb, q);
#pragma unroll
    for (int rs = 0; rs < 2; rs++)
#pragma unroll
        for (int tn = 0; tn < 2; tn++) {     // + U residual from BUF2
            float* e = acc + rs * 16 + tn * 8;
            int row = m0 + 16 * rs + g;
            uint32_t a0 = B2 + (uint32_t)(row * 256) + SWC((cb >> 3) + 2 * tn, g) + 4 * q;
            uint32_t a1 = B2 + (uint32_t)(row * 256) + SWC((cb >> 3) + 2 * tn + 1, g) + 4 * q;
            uint32_t h, l;
            LDS32(h, a0); LDS32(l, a0 + 32768);
            float2 hf = bf2f2(h), lf = bf2f2(l);
            e[0] += hf.x + lf.x; e[1] += hf.y + lf.y;
            LDS32(h, a0 + 2048); LDS32(l, a0 + 2048 + 32768);
            hf = bf2f2(h); lf = bf2f2(l);
            e[2] += hf.x + lf.x; e[3] += hf.y + lf.y;
            LDS32(h, a1); LDS32(l, a1 + 32768);
            hf = bf2f2(h); lf = bf2f2(l);
            e[4] += hf.x + lf.x; e[5] += hf.y + lf.y;
            LDS32(h, a1 + 2048); LDS32(l, a1 + 2048 + 32768);
            hf = bf2f2(h); lf = bf2f2(l);
            e[6] += hf.x + lf.x; e[7] += hf.y + lf.y;
        }
    {   // 1-round final LN
        float s[4] = {0,0,0,0}, qq[4] = {0,0,0,0};
#pragma unroll
        for (int rs = 0; rs < 2; rs++)
#pragma unroll
            for (int tn = 0; tn < 2; tn++) {
                float* e = acc + rs * 16 + tn * 8;
                s[2*rs]   += e[0] + e[1] + e[4] + e[5];
                s[2*rs+1] += e[2] + e[3] + e[6] + e[7];
                qq[2*rs]   += e[0]*e[0] + e[1]*e[1] + e[4]*e[4] + e[5]*e[5];
                qq[2*rs+1] += e[2]*e[2] + e[3]*e[3] + e[6]*e[6] + e[7]*e[7];
            }
        QRED(s[0]); QRED(s[1]); QRED(s[2]); QRED(s[3]);
        QRED(qq[0]); QRED(qq[1]); QRED(qq[2]); QRED(qq[3]);
        __syncthreads();                                   // W2 reads done before WS stores
#pragma unroll
        for (int i = 0; i < 4; i++) {
            STSF(SCA + (uint32_t)(4 * (rA + 8 * i) + wn) * 4, s[i]);
            STSF(WS + (uint32_t)(4 * (rA + 8 * i) + wn) * 4, qq[i]);
        }
        __syncthreads();
        float mu[4], iv[4];
#pragma unroll
        for (int i = 0; i < 4; i++) {
            float a0, a1, a2, a3, c0, c1, c2, c3;
            uint32_t bs = SCA + (uint32_t)(4 * (rA + 8 * i)) * 4;
            uint32_t bw = WS + (uint32_t)(4 * (rA + 8 * i)) * 4;
            LDSF(a0, bs); LDSF(a1, bs + 4); LDSF(a2, bs + 8); LDSF(a3, bs + 12);
            LDSF(c0, bw); LDSF(c1, bw + 4); LDSF(c2, bw + 8); LDSF(c3, bw + 12);
            mu[i] = (a0 + a1 + a2 + a3) * 0.0078125f;
            float var = (c0 + c1 + c2 + c3) * 0.0078125f - mu[i] * mu[i];
            iv[i] = rsqrtf(var + 1e-5f);
        }
#pragma unroll
        for (int rs = 0; rs < 2; rs++)
#pragma unroll
            for (int tn = 0; tn < 2; tn++) {
                float* e = acc + rs * 16 + tn * 8;
                int c = cb + 16 * tn + 2 * q;
                size_t ra = (size_t)(rA + 16 * rs), rb = ra + 8;
                *(float2*)(ob + ra * TSTRIDE + c) =
                    make_float2((e[0] - mu[2*rs]) * iv[2*rs], (e[1] - mu[2*rs]) * iv[2*rs]);
                *(float2*)(ob + rb * TSTRIDE + c) =
                    make_float2((e[2] - mu[2*rs+1]) * iv[2*rs+1], (e[3] - mu[2*rs+1]) * iv[2*rs+1]);
                *(float2*)(ob + ra * TSTRIDE + c + 8) =
                    make_float2((e[4] - mu[2*rs]) * iv[2*rs], (e[5] - mu[2*rs]) * iv[2*rs]);
                *(float2*)(ob + rb * TSTRIDE + c + 8) =
                    make_float2((e[6] - mu[2*rs+1]) * iv[2*rs+1], (e[7] - mu[2*rs+1]) * iv[2*rs+1]);
            }
    }
}

extern "C" void kernel_launch(void* const* d_in, const int* in_sizes, int n_in,
                              void* d_out, int out_size) {
    const float* x  = (const float*)d_in[0];
    const float* te = (const float*)d_in[1];
    const float* wq = (const float*)d_in[2];
    const float* bq = (const float*)d_in[3];
    const float* wk = (const float*)d_in[4];
    const float* bk = (const float*)d_in[5];
    const float* wv = (const float*)d_in[6];
    const float* bv = (const float*)d_in[7];
    const float* wo = (const float*)d_in[8];
    const float* bo = (const float*)d_in[9];
    const float* w1 = (const float*)d_in[10];
    const float* b1 = (const float*)d_in[11];
    const float* w2 = (const float*)d_in[12];
    const float* b2 = (const float*)d_in[13];
    float* out = (float*)d_out;

    prep_w<<<6, 256>>>(wk, wq, wv, wo, w1, w2);
    cudaFuncSetAttribute(fused_hmma9, cudaFuncAttributeMaxDynamicSharedMemorySize, SMEM_TOT);
    fused_hmma9<<<4096, THREADS, SMEM_TOT>>>(x, te, bq, bk, bv, bo, b1, b2, out);
}

// round 15
// speedup vs baseline: 1.0141x; 1.0141x over previous
#include <cuda_runtime.h>
#include <cuda_bf16.h>
#include <cstdint>

#define TSTRIDE 32768
#define THREADS 512

// smem byte offsets
#define BUF0 0u
#define BUF1 65536u
#define BUF2 131072u
#define WOFF 196608u
#define SCOFF 229376u     // SCA: 512 floats (128 rows x 4 quadrants)
#define SMEM_TOT 231424

// Weight images: [wk, wq, wv, wo, w1, w2], each = [hi 32KB | lo 32KB]
__device__ __align__(16) unsigned char g_w[6][65536];

#define SWC(c, r7) ((uint32_t)(((((c) ^ (r7)) & 7) | ((c) & 8)) << 4))

// S-tile assignment (per-warp (sm,sn) bijection, balanced across SMSPs)
#define SMTAB 0x1000212133213320ull
#define SNTAB 0x3321322131102000ull

__device__ __forceinline__ uint32_t smem_u32(const void* p) {
    uint32_t a;
    asm("{ .reg .u64 t; cvta.to.shared.u64 t, %1; cvt.u32.u64 %0, t; }" : "=r"(a) : "l"(p));
    return a;
}
__device__ __forceinline__ uint32_t f2bf2(float a, float b) {   // lo=a, hi=b
    uint32_t r;
    asm("cvt.rn.bf16x2.f32 %0, %1, %2;" : "=r"(r) : "f"(b), "f"(a));
    return r;
}
__device__ __forceinline__ float2 bf2f2(uint32_t u) {
    __nv_bfloat162 h = *reinterpret_cast<__nv_bfloat162*>(&u);
    return __bfloat1622float2(h);
}
__device__ __forceinline__ void ldsm4(uint32_t* r, uint32_t a) {
    asm volatile("ldmatrix.sync.aligned.m8n8.x4.shared.b16 {%0,%1,%2,%3}, [%4];"
        : "=r"(r[0]), "=r"(r[1]), "=r"(r[2]), "=r"(r[3]) : "r"(a));
}
__device__ __forceinline__ void mma_bf16(float* d, const uint32_t* a, uint32_t b0, uint32_t b1) {
    asm volatile("mma.sync.aligned.m16n8k16.row.col.f32.bf16.bf16.f32 "
        "{%0,%1,%2,%3}, {%4,%5,%6,%7}, {%8,%9}, {%0,%1,%2,%3};"
        : "+f"(d[0]), "+f"(d[1]), "+f"(d[2]), "+f"(d[3])
        : "r"(a[0]), "r"(a[1]), "r"(a[2]), "r"(a[3]), "r"(b0), "r"(b1));
}
#define STS32(a, v)  asm volatile("st.shared.b32 [%0], %1;" :: "r"(a), "r"(v) : "memory")
#define STS128(a, v0, v1, v2, v3) \
    asm volatile("st.shared.v4.b32 [%0], {%1,%2,%3,%4};" \
        :: "r"(a), "r"(v0), "r"(v1), "r"(v2), "r"(v3) : "memory")
#define LDS32(v, a)  asm volatile("ld.shared.b32 %0, [%1];" : "=r"(v) : "r"(a))
#define STSF(a, v)   asm volatile("st.shared.f32 [%0], %1;" :: "r"(a), "f"(v) : "memory")
#define LDSF(v, a)   asm volatile("ld.shared.f32 %0, [%1];" : "=f"(v) : "r"(a))
#define CP16(d, s) \
    asm volatile("cp.async.cg.shared.global [%0], [%1], 16;" :: "r"(d), "l"(s) : "memory")
#define CP_COMMIT  asm volatile("cp.async.commit_group;" ::: "memory")
#define CP_WAITALL asm volatile("cp.async.wait_group 0;" ::: "memory")
#define QRED(v) do { v += __shfl_xor_sync(~0u, v, 1); v += __shfl_xor_sync(~0u, v, 2); } while (0)

// ============ prep kernel ============
__global__ void prep_w(const float* __restrict__ wk, const float* __restrict__ wq,
                       const float* __restrict__ wv, const float* __restrict__ wo,
                       const float* __restrict__ w1, const float* __restrict__ w2) {
    const float* ws[6] = {wk, wq, wv, wo, w1, w2};
    const float* src = ws[blockIdx.x];
    unsigned char* dst = g_w[blockIdx.x];
    for (int e = threadIdx.x; e < 16384; e += blockDim.x) {
        int f = e >> 7, k = e & 127;
        float val = src[k * 128 + f];            // W^T[f][k]
        __nv_bfloat16 h = __float2bfloat16(val);
        __nv_bfloat16 l = __float2bfloat16(val - __bfloat162float(h));
        uint32_t off = (uint32_t)f * 256 + SWC(k >> 3, f & 7) + (uint32_t)(k & 7) * 2;
        *(__nv_bfloat16*)(dst + off) = h;
        *(__nv_bfloat16*)(dst + 32768 + off) = l;
    }
}

// ============ cp.async staging ============
__device__ __forceinline__ void cpa32(uint32_t dst, const unsigned char* src, int tid) {
#pragma unroll
    for (int i = 0; i < 4; i++)
        CP16(dst + (uint32_t)(tid * 16 + i * 8192), src + tid * 16 + i * 8192);
}
__device__ __forceinline__ void cpa64(uint32_t dst, const unsigned char* src, int tid) {
#pragma unroll
    for (int i = 0; i < 8; i++)
        CP16(dst + (uint32_t)(tid * 16 + i * 8192), src + tid * 16 + i * 8192);
}

// ============ GEMM core: 32x32 warp tile, round-robin mma order ============
__device__ __forceinline__ void gchunk(uint32_t ahb, uint32_t alb, uint32_t bhb,
                                       uint32_t blb, float* acc,
                                       uint32_t ar0, uint32_t ar1,
                                       uint32_t br0, uint32_t br1, uint32_t csw) {
    uint32_t a0h[4], a0l[4], a1h[4], a1l[4];
    uint32_t b0h[4], b0l[4], b1h[4], b1l[4];
    ldsm4(a0h, ahb + ar0 + csw);
    ldsm4(a1h, ahb + ar1 + csw);
    ldsm4(b0h, bhb + br0 + csw);
    ldsm4(b1h, bhb + br1 + csw);
    ldsm4(a0l, alb + ar0 + csw);
    ldsm4(a1l, alb + ar1 + csw);
    ldsm4(b0l, blb + br0 + csw);
    ldsm4(b1l, blb + br1 + csw);
    mma_bf16(acc+0,  a0h, b0h[0], b0h[2]); mma_bf16(acc+4,  a0h, b0h[1], b0h[3]);
    mma_bf16(acc+8,  a0h, b1h[0], b1h[2]); mma_bf16(acc+12, a0h, b1h[1], b1h[3]);
    mma_bf16(acc+16, a1h, b0h[0], b0h[2]); mma_bf16(acc+20, a1h, b0h[1], b0h[3]);
    mma_bf16(acc+24, a1h, b1h[0], b1h[2]); mma_bf16(acc+28, a1h, b1h[1], b1h[3]);
    mma_bf16(acc+0,  a0l, b0h[0], b0h[2]); mma_bf16(acc+4,  a0l, b0h[1], b0h[3]);
    mma_bf16(acc+8,  a0l, b1h[0], b1h[2]); mma_bf16(acc+12, a0l, b1h[1], b1h[3]);
    mma_bf16(acc+16, a1l, b0h[0], b0h[2]); mma_bf16(acc+20, a1l, b0h[1], b0h[3]);
    mma_bf16(acc+24, a1l, b1h[0], b1h[2]); mma_bf16(acc+28, a1l, b1h[1], b1h[3]);
    mma_bf16(acc+0,  a0h, b0l[0], b0l[2]); mma_bf16(acc+4,  a0h, b0l[1], b0l[3]);
    mma_bf16(acc+8,  a0h, b1l[0], b1l[2]); mma_bf16(acc+12, a0h, b1l[1], b1l[3]);
    mma_bf16(acc+16, a1h, b0l[0], b0l[2]); mma_bf16(acc+20, a1h, b0l[1], b0l[3]);
    mma_bf16(acc+24, a1h, b1l[0], b1l[2]); mma_bf16(acc+28, a1h, b1l[1], b1l[3]);
}

__device__ __forceinline__ void gfull(uint32_t ahb, uint32_t alb, uint32_t bhb,
                                      uint32_t blb, float* acc, int m0, int cb,
                                      int noff, int khalf) {
    const int rr = noff & 7;
    const uint32_t ar0 = (uint32_t)((m0 + noff) * 256), ar1 = ar0 + 4096;
    const uint32_t br0 = (uint32_t)((cb + noff) * 256), br1 = br0 + 4096;
#pragma unroll
    for (int j = 0; j < 8; j++)
        gchunk(ahb, alb, bhb, blb, acc, ar0, ar1, br0, br1, SWC(2 * j + khalf, rr));
}
__device__ __forceinline__ void gvar(uint32_t ahb, uint32_t alb, uint32_t bhb,
                                     uint32_t blb, float* acc, int m0, int cb,
                                     int noff, int khalf, int jmax) {
    const int rr = noff & 7;
    const uint32_t ar0 = (uint32_t)((m0 + noff) * 256), ar1 = ar0 + 4096;
    const uint32_t br0 = (uint32_t)((cb + noff) * 256), br1 = br0 + 4096;
#pragma unroll 2
    for (int j = 0; j < jmax; j++)
        gchunk(ahb, alb, bhb, blb, acc, ar0, ar1, br0, br1, SWC(2 * j + khalf, rr));
}
// acc += (Ah+Al) @ B (single B half), round-robin
__device__ __forceinline__ void gAB(uint32_t ahb, uint32_t alb, uint32_t bb,
                                    float* acc, int m0, int cb, int noff, int khalf) {
    const int rr = noff & 7;
    const uint32_t ar0 = (uint32_t)((m0 + noff) * 256), ar1 = ar0 + 4096;
    const uint32_t br0 = (uint32_t)((cb + noff) * 256), br1 = br0 + 4096;
#pragma unroll
    for (int j = 0; j < 8; j++) {
        const uint32_t csw = SWC(2 * j + khalf, rr);
        uint32_t a0h[4], a0l[4], a1h[4], a1l[4], b0[4], b1[4];
        ldsm4(a0h, ahb + ar0 + csw); ldsm4(a1h, ahb + ar1 + csw);
        ldsm4(b0, bb + br0 + csw);   ldsm4(b1, bb + br1 + csw);
        ldsm4(a0l, alb + ar0 + csw); ldsm4(a1l, alb + ar1 + csw);
        mma_bf16(acc+0,  a0h, b0[0], b0[2]); mma_bf16(acc+4,  a0h, b0[1], b0[3]);
        mma_bf16(acc+8,  a0h, b1[0], b1[2]); mma_bf16(acc+12, a0h, b1[1], b1[3]);
        mma_bf16(acc+16, a1h, b0[0], b0[2]); mma_bf16(acc+20, a1h, b0[1], b0[3]);
        mma_bf16(acc+24, a1h, b1[0], b1[2]); mma_bf16(acc+28, a1h, b1[1], b1[3]);
        mma_bf16(acc+0,  a0l, b0[0], b0[2]); mma_bf16(acc+4,  a0l, b0[1], b0[3]);
        mma_bf16(acc+8,  a0l, b1[0], b1[2]); mma_bf16(acc+12, a0l, b1[1], b1[3]);
        mma_bf16(acc+16, a1l, b0[0], b0[2]); mma_bf16(acc+20, a1l, b0[1], b0[3]);
        mma_bf16(acc+24, a1l, b1[0], b1[2]); mma_bf16(acc+28, a1l, b1[1], b1[3]);
    }
}
// acc += A @ B (single A, single B half)
__device__ __forceinline__ void gA(uint32_t ab, uint32_t bb, float* acc,
                                   int m0, int cb, int noff, int khalf) {
    const int rr = noff & 7;
    const uint32_t ar0 = (uint32_t)((m0 + noff) * 256), ar1 = ar0 + 4096;
    const uint32_t br0 = (uint32_t)((cb + noff) * 256), br1 = br0 + 4096;
#pragma unroll
    for (int j = 0; j < 8; j++) {
        const uint32_t csw = SWC(2 * j + khalf, rr);
        uint32_t a0[4], a1[4], b0[4], b1[4];
        ldsm4(a0, ab + ar0 + csw); ldsm4(a1, ab + ar1 + csw);
        ldsm4(b0, bb + br0 + csw); ldsm4(b1, bb + br1 + csw);
        mma_bf16(acc+0,  a0, b0[0], b0[2]); mma_bf16(acc+4,  a0, b0[1], b0[3]);
        mma_bf16(acc+8,  a0, b1[0], b1[2]); mma_bf16(acc+12, a0, b1[1], b1[3]);
        mma_bf16(acc+16, a1, b0[0], b0[2]); mma_bf16(acc+20, a1, b0[1], b0[3]);
        mma_bf16(acc+24, a1, b1[0], b1[2]); mma_bf16(acc+28, a1, b1[1], b1[3]);
    }
}

__device__ __forceinline__ void zacc(float* acc) {
#pragma unroll
    for (int i = 0; i < 32; i++) acc[i] = 0.0f;
}

// store acc (rows m0+16rs+g, +8; cols cb..cb+32) as hi/lo bf16 image
__device__ __forceinline__ void simg(uint32_t ibase, const float* acc, int m0, int cb,
                                     int g, int q) {
#pragma unroll
    for (int rs = 0; rs < 2; rs++)
#pragma unroll
        for (int tn = 0; tn < 2; tn++) {
            const float* e = acc + rs * 16 + tn * 8;
            int row = m0 + 16 * rs + g;
            uint32_t a0 = ibase + (uint32_t)(row * 256) + SWC((cb >> 3) + 2 * tn, g) + 4 * q;
            uint32_t a1 = ibase + (uint32_t)(row * 256) + SWC((cb >> 3) + 2 * tn + 1, g) + 4 * q;
            uint32_t h0 = f2bf2(e[0], e[1]), h1 = f2bf2(e[2], e[3]);
            float2 f0 = bf2f2(h0), f1 = bf2f2(h1);
            uint32_t l0 = f2bf2(e[0] - f0.x, e[1] - f0.y);
            uint32_t l1 = f2bf2(e[2] - f1.x, e[3] - f1.y);
            STS32(a0, h0);        STS32(a0 + 32768, l0);
            STS32(a0 + 2048, h1); STS32(a0 + 2048 + 32768, l1);
            uint32_t h2 = f2bf2(e[4], e[5]), h3 = f2bf2(e[6], e[7]);
            float2 f2 = bf2f2(h2), f3 = bf2f2(h3);
            uint32_t l2 = f2bf2(e[4] - f2.x, e[5] - f2.y);
            uint32_t l3 = f2bf2(e[6] - f3.x, e[7] - f3.y);
            STS32(a1, h2);        STS32(a1 + 32768, l2);
            STS32(a1 + 2048, h3); STS32(a1 + 2048 + 32768, l3);
        }
}

__device__ __forceinline__ void biasc(float* acc, const float* __restrict__ bias,
                                      int cb, int q) {
#pragma unroll
    for (int rs = 0; rs < 2; rs++)
#pragma unroll
        for (int tn = 0; tn < 2; tn++) {
            float* e = acc + rs * 16 + tn * 8;
            float2 b0 = __ldg((const float2*)(bias + cb + 16 * tn + 2 * q));
            float2 b1 = __ldg((const float2*)(bias + cb + 16 * tn + 8 + 2 * q));
            e[0] += b0.x; e[1] += b0.y; e[2] += b0.x; e[3] += b0.y;
            e[4] += b1.x; e[5] += b1.y; e[6] += b1.x; e[7] += b1.y;
        }
}

// ============ main kernel ============
__global__ void __launch_bounds__(THREADS, 1)
fused_hmmaA(const float* __restrict__ x, const float* __restrict__ te,
            const float* __restrict__ bq, const float* __restrict__ bk,
            const float* __restrict__ bv, const float* __restrict__ bo,
            const float* __restrict__ b1, const float* __restrict__ b2,
            float* __restrict__ out) {
    extern __shared__ char smc[];
    const uint32_t sb = smem_u32(smc);
    const uint32_t B0 = sb + BUF0, B1 = sb + BUF1, B2 = sb + BUF2, W = sb + WOFF;
    const uint32_t SCA = sb + SCOFF;
    const uint32_t WS = W;                // LN sumsq scratch (W dead at LN time)

    const int tid = threadIdx.x, lane = tid & 31, w = tid >> 5;
    const int wm = w >> 2, wn = w & 3;
    const int m0 = 32 * wm, cb = 32 * wn;
    const int g = lane >> 2, q = lane & 3;
    const int noff = ((lane >> 3) & 1) * 8 + (lane & 7);
    const int khalf = lane >> 4;
    const int rA = m0 + g;                // rows rA, +8, +16, +24

    const int bn = blockIdx.x, b = bn >> 8, n = bn & 255;
    const float* xb  = x  + (size_t)b * 128 * TSTRIDE + (size_t)n * 128;
    const float* teb = te + (size_t)b * 128 * TSTRIDE + (size_t)n * 128;
    float* ob = out + (size_t)b * 128 * TSTRIDE + (size_t)n * 128;

    // G0: prefetch Wk -> BUF2, Wv -> BUF1, Wq-hi -> W
    cpa64(B2, g_w[0], tid);
    cpa64(B1, g_w[2], tid);
    cpa32(W, g_w[1], tid);
    CP_COMMIT;

    // ---- build X = x+te hi/lo image -> BUF0 ----
    {
        int row = tid >> 2, quarter = tid & 3;
        const float4* xr = (const float4*)(xb  + (size_t)row * TSTRIDE + 32 * quarter);
        const float4* tr = (const float4*)(teb + (size_t)row * TSTRIDE + 32 * quarter);
#pragma unroll
        for (int ci = 0; ci < 4; ci++) {
            float4 a = xr[2*ci], c = tr[2*ci], a2 = xr[2*ci+1], c2 = tr[2*ci+1];
            float v0 = a.x + c.x, v1 = a.y + c.y, v2 = a.z + c.z, v3 = a.w + c.w;
            float v4 = a2.x + c2.x, v5 = a2.y + c2.y, v6 = a2.z + c2.z, v7 = a2.w + c2.w;
            uint32_t h0 = f2bf2(v0, v1), h1 = f2bf2(v2, v3);
            uint32_t h2 = f2bf2(v4, v5), h3 = f2bf2(v6, v7);
            float2 e0 = bf2f2(h0), e1 = bf2f2(h1), e2 = bf2f2(h2), e3 = bf2f2(h3);
            uint32_t l0 = f2bf2(v0 - e0.x, v1 - e0.y), l1 = f2bf2(v2 - e1.x, v3 - e1.y);
            uint32_t l2 = f2bf2(v4 - e2.x, v5 - e2.y), l3 = f2bf2(v6 - e3.x, v7 - e3.y);
            uint32_t addr = B0 + (uint32_t)row * 256 + SWC(4 * quarter + ci, row & 7);
            STS128(addr, h0, h1, h2, h3);
            STS128(addr + 32768, l0, l1, l2, l3);
        }
    }
    CP_WAITALL;
    __syncthreads();

    float acc[32];

    // ==== Phase 1: K = X @ Wk -> BUF2 ====
    zacc(acc);
    gfull(B0, B0 + 32768, B2, B2 + 32768, acc, m0, cb, noff, khalf);
    biasc(acc, bk, cb, q);
    __syncthreads();
    simg(B2, acc, m0, cb, g, q);

    // ==== Phase 2: V^T = Wv^T @ X -> BUF1 ====
    zacc(acc);
    gfull(B1, B1 + 32768, B0, B0 + 32768, acc, m0, cb, noff, khalf);
    {
        float bv0 = __ldg(bv + rA), bv1 = __ldg(bv + rA + 8);
        float bv2 = __ldg(bv + rA + 16), bv3 = __ldg(bv + rA + 24);
#pragma unroll
        for (int tn = 0; tn < 2; tn++) {
#pragma unroll
            for (int j = 0; j < 4; j++) {
                acc[8*tn + j] += (j < 2) ? bv0 : bv1;
                acc[8*tn + 4 + j] += (j < 2) ? bv0 : bv1;
                acc[16 + 8*tn + j] += (j < 2) ? bv2 : bv3;
                acc[16 + 8*tn + 4 + j] += (j < 2) ? bv2 : bv3;
            }
        }
    }
    __syncthreads();
    simg(B1, acc, m0, cb, g, q);

    // ==== Phase 3: Q = X @ Wq -> BUF0 (Wq-lo prefetched in registers) ====
    {
        uint4 p[4];
        {
            const uint4* s = (const uint4*)(g_w[1] + 32768);
#pragma unroll
            for (int i = 0; i < 4; i++) p[i] = s[tid + 512 * i];
        }
        zacc(acc);
        gAB(B0, B0 + 32768, W, acc, m0, cb, noff, khalf);  // (Xh+Xl)@Wqh
        __syncthreads();                                   // Wq-hi reads done
        {
            uint4* d = (uint4*)(smc + WOFF);
#pragma unroll
            for (int i = 0; i < 4; i++) d[tid + 512 * i] = p[i];
        }
        __syncthreads();                                   // Wq-lo visible
        gA(B0, W, acc, m0, cb, noff, khalf);               // Xh@Wql
        biasc(acc, bq, cb, q);
        __syncthreads();                                   // X + Wq-lo reads done
        cpa32(W, g_w[3], tid); CP_COMMIT;                  // G2: Wo-hi -> W
        simg(B0, acc, m0, cb, g, q);                       // Q image
        __syncthreads();
    }

    // ==== Phase 4: S (assigned tile) -> causal softmax -> P -> BUF0 ====
    {
        const int sm = (int)((SMTAB >> (4 * w)) & 7);
        const int sn = (int)((SNTAB >> (4 * w)) & 7);
        const bool masked = sn > sm;
        const int sm0 = 32 * sm, scb = 32 * sn;
        const int rS = sm0 + g;
        zacc(acc);
        if (!masked)
            gfull(B0, B0 + 32768, B2, B2 + 32768, acc, sm0, scb, noff, khalf);
        float s[4] = {0, 0, 0, 0};
        if (!masked) {
#pragma unroll
            for (int rs = 0; rs < 2; rs++)
#pragma unroll
                for (int tn = 0; tn < 2; tn++) {
                    float* e = acc + rs * 16 + tn * 8;
                    int ra = rS + 16 * rs, rb = ra + 8;
                    int c0 = scb + 16 * tn + 2 * q;
                    int c1 = c0 + 8;
                    float p0 = (c0     <= ra) ? __expf(e[0] * 0.25f) : 0.0f;
                    float p1 = (c0 + 1 <= ra) ? __expf(e[1] * 0.25f) : 0.0f;
                    float p2 = (c0     <= rb) ? __expf(e[2] * 0.25f) : 0.0f;
                    float p3 = (c0 + 1 <= rb) ? __expf(e[3] * 0.25f) : 0.0f;
                    float p4 = (c1     <= ra) ? __expf(e[4] * 0.25f) : 0.0f;
                    float p5 = (c1 + 1 <= ra) ? __expf(e[5] * 0.25f) : 0.0f;
                    float p6 = (c1     <= rb) ? __expf(e[6] * 0.25f) : 0.0f;
                    float p7 = (c1 + 1 <= rb) ? __expf(e[7] * 0.25f) : 0.0f;
                    e[0]=p0; e[1]=p1; e[2]=p2; e[3]=p3; e[4]=p4; e[5]=p5; e[6]=p6; e[7]=p7;
                    s[2*rs]   += p0 + p1 + p4 + p5;
                    s[2*rs+1] += p2 + p3 + p6 + p7;
                }
        }
        QRED(s[0]); QRED(s[1]); QRED(s[2]); QRED(s[3]);
        STSF(SCA + (uint32_t)(4 * rS + sn) * 4, s[0]);
        STSF(SCA + (uint32_t)(4 * (rS + 8) + sn) * 4, s[1]);
        STSF(SCA + (uint32_t)(4 * (rS + 16) + sn) * 4, s[2]);
        STSF(SCA + (uint32_t)(4 * (rS + 24) + sn) * 4, s[3]);
        __syncthreads();                                   // K,Q reads + sums ALL done
        cpa32(B2 + 32768, g_w[3] + 32768, tid); CP_COMMIT; // G3: Wo-lo -> B2lo (K now dead)
        if (!masked) {
            float inv[4];
#pragma unroll
            for (int i = 0; i < 4; i++) {
                float a0, a1, a2, a3;
                uint32_t base = SCA + (uint32_t)(4 * (rS + 8 * i)) * 4;
                LDSF(a0, base); LDSF(a1, base + 4); LDSF(a2, base + 8); LDSF(a3, base + 12);
                inv[i] = 1.0f / (a0 + a1 + a2 + a3);
            }
#pragma unroll
            for (int rs = 0; rs < 2; rs++)
#pragma unroll
                for (int tn = 0; tn < 2; tn++) {
                    float* e = acc + rs * 16 + tn * 8;
                    e[0] *= inv[2*rs]; e[1] *= inv[2*rs];
                    e[2] *= inv[2*rs+1]; e[3] *= inv[2*rs+1];
                    e[4] *= inv[2*rs]; e[5] *= inv[2*rs];
                    e[6] *= inv[2*rs+1]; e[7] *= inv[2*rs+1];
                }
            simg(B0, acc, sm0, scb, g, q);                 // P image (lower tiles only)
        }
        __syncthreads();
    }

    // ==== Phase 5: AO = P @ V (k bounded: jmax = 2wm+2) -> BUF0 ====
    zacc(acc);
    gvar(B0, B0 + 32768, B1, B1 + 32768, acc, m0, cb, noff, khalf, 2 * wm + 2);
    __syncthreads();
    simg(B0, acc, m0, cb, g, q);                           // AO image
    CP_WAITALL;
    __syncthreads();
    cpa64(B1, g_w[4], tid); CP_COMMIT;                     // G4: W1 -> BUF1

    // ==== Phase 6: U = LN(AO @ Wo + bo + (x+te)) -> BUF2 ====
    zacc(acc);
    gfull(B0, B0 + 32768, W, B2 + 32768, acc, m0, cb, noff, khalf);
    biasc(acc, bo, cb, q);
#pragma unroll
    for (int rs = 0; rs < 2; rs++)
#pragma unroll
        for (int tn = 0; tn < 2; tn++) {
            float* e = acc + rs * 16 + tn * 8;
            int c = cb + 16 * tn + 2 * q;
            size_t ra = (size_t)(rA + 16 * rs), rb = ra + 8;
            float2 xa = *(const float2*)(xb + ra * TSTRIDE + c);
            float2 ta = *(const float2*)(teb + ra * TSTRIDE + c);
            e[0] += xa.x + ta.x; e[1] += xa.y + ta.y;
            float2 xc = *(const float2*)(xb + rb * TSTRIDE + c);
            float2 tc = *(const float2*)(teb + rb * TSTRIDE + c);
            e[2] += xc.x + tc.x; e[3] += xc.y + tc.y;
            float2 xe = *(const float2*)(xb + ra * TSTRIDE + c + 8);
            float2 tee = *(const float2*)(teb + ra * TSTRIDE + c + 8);
            e[4] += xe.x + tee.x; e[5] += xe.y + tee.y;
            float2 xg = *(const float2*)(xb + rb * TSTRIDE + c + 8);
            float2 tg = *(const float2*)(teb + rb * TSTRIDE + c + 8);
            e[6] += xg.x + tg.x; e[7] += xg.y + tg.y;
        }
    {   // 1-round LN: sum -> SCA, sumsq -> WS
        float s[4] = {0,0,0,0}, qq[4] = {0,0,0,0};
#pragma unroll
        for (int rs = 0; rs < 2; rs++)
#pragma unroll
            for (int tn = 0; tn < 2; tn++) {
                float* e = acc + rs * 16 + tn * 8;
                s[2*rs]   += e[0] + e[1] + e[4] + e[5];
                s[2*rs+1] += e[2] + e[3] + e[6] + e[7];
                qq[2*rs]   += e[0]*e[0] + e[1]*e[1] + e[4]*e[4] + e[5]*e[5];
                qq[2*rs+1] += e[2]*e[2] + e[3]*e[3] + e[6]*e[6] + e[7]*e[7];
            }
        QRED(s[0]); QRED(s[1]); QRED(s[2]); QRED(s[3]);
        QRED(qq[0]); QRED(qq[1]); QRED(qq[2]); QRED(qq[3]);
#pragma unroll
        for (int i = 0; i < 4; i++) {
            STSF(SCA + (uint32_t)(4 * (rA + 8 * i) + wn) * 4, s[i]);
            STSF(WS + (uint32_t)(4 * (rA + 8 * i) + wn) * 4, qq[i]);
        }
        __syncthreads();
        float mu[4], iv[4];
#pragma unroll
        for (int i = 0; i < 4; i++) {
            float a0, a1, a2, a3, c0, c1, c2, c3;
            uint32_t bs = SCA + (uint32_t)(4 * (rA + 8 * i)) * 4;
            uint32_t bw = WS + (uint32_t)(4 * (rA + 8 * i)) * 4;
            LDSF(a0, bs); LDSF(a1, bs + 4); LDSF(a2, bs + 8); LDSF(a3, bs + 12);
            LDSF(c0, bw); LDSF(c1, bw + 4); LDSF(c2, bw + 8); LDSF(c3, bw + 12);
            mu[i] = (a0 + a1 + a2 + a3) * 0.0078125f;
            float var = (c0 + c1 + c2 + c3) * 0.0078125f - mu[i] * mu[i];
            iv[i] = rsqrtf(var + 1e-5f);
        }
#pragma unroll
        for (int rs = 0; rs < 2; rs++)
#pragma unroll
            for (int tn = 0; tn < 2; tn++) {
                float* e = acc + rs * 16 + tn * 8;
                e[0] = (e[0] - mu[2*rs]) * iv[2*rs];   e[1] = (e[1] - mu[2*rs]) * iv[2*rs];
                e[4] = (e[4] - mu[2*rs]) * iv[2*rs];   e[5] = (e[5] - mu[2*rs]) * iv[2*rs];
                e[2] = (e[2] - mu[2*rs+1]) * iv[2*rs+1]; e[3] = (e[3] - mu[2*rs+1]) * iv[2*rs+1];
                e[6] = (e[6] - mu[2*rs+1]) * iv[2*rs+1]; e[7] = (e[7] - mu[2*rs+1]) * iv[2*rs+1];
            }
    }
    __syncthreads();                                       // WS reads done before G5
    cpa32(W, g_w[5], tid); CP_COMMIT;                      // G5: W2-hi -> W
    simg(B2, acc, m0, cb, g, q);                           // U image
    CP_WAITALL;
    __syncthreads();

    // ==== Phase 7: H = relu(U @ W1 + b1) -> BUF0 ====
    zacc(acc);
    gfull(B2, B2 + 32768, B1, B1 + 32768, acc, m0, cb, noff, khalf);
    biasc(acc, b1, cb, q);
#pragma unroll
    for (int i = 0; i < 32; i++) acc[i] = fmaxf(acc[i], 0.0f);
    __syncthreads();
    cpa32(B1 + 32768, g_w[5] + 32768, tid); CP_COMMIT;     // G6: W2-lo -> BUF1lo
    simg(B0, acc, m0, cb, g, q);                           // H image
    CP_WAITALL;
    __syncthreads();

    // ==== Phase 8: out = LN(H @ W2 + b2 + U) -> gmem ====
    zacc(acc);
    gfull(B0, B0 + 32768, W, B1 + 32768, acc, m0, cb, noff, khalf);
    biasc(acc, b2, cb, q);
#pragma unroll
    for (int rs = 0; rs < 2; rs++)
#pragma unroll
        for (int tn = 0; tn < 2; tn++) {     // + U residual from BUF2
            float* e = acc + rs * 16 + tn * 8;
            int row = m0 + 16 * rs + g;
            uint32_t a0 = B2 + (uint32_t)(row * 256) + SWC((cb >> 3) + 2 * tn, g) + 4 * q;
            uint32_t a1 = B2 + (uint32_t)(row * 256) + SWC((cb >> 3) + 2 * tn + 1, g) + 4 * q;
            uint32_t h, l;
            LDS32(h, a0); LDS32(l, a0 + 32768);
            float2 hf = bf2f2(h), lf = bf2f2(l);
            e[0] += hf.x + lf.x; e[1] += hf.y + lf.y;
            LDS32(h, a0 + 2048); LDS32(l, a0 + 2048 + 32768);
            hf = bf2f2(h); lf = bf2f2(l);
            e[2] += hf.x + lf.x; e[3] += hf.y + lf.y;
            LDS32(h, a1); LDS32(l, a1 + 32768);
            hf = bf2f2(h); lf = bf2f2(l);
            e[4] += hf.x + lf.x; e[5] += hf.y + lf.y;
            LDS32(h, a1 + 2048); LDS32(l, a1 + 2048 + 32768);
            hf = bf2f2(h); lf = bf2f2(l);
            e[6] += hf.x + lf.x; e[7] += hf.y + lf.y;
        }
    {   // 1-round final LN
        float s[4] = {0,0,0,0}, qq[4] = {0,0,0,0};
#pragma unroll
        for (int rs = 0; rs < 2; rs++)
#pragma unroll
            for (int tn = 0; tn < 2; tn++) {
                float* e = acc + rs * 16 + tn * 8;
                s[2*rs]   += e[0] + e[1] + e[4] + e[5];
                s[2*rs+1] += e[2] + e[3] + e[6] + e[7];
                qq[2*rs]   += e[0]*e[0] + e[1]*e[1] + e[4]*e[4] + e[5]*e[5];
                qq[2*rs+1] += e[2]*e[2] + e[3]*e[3] + e[6]*e[6] + e[7]*e[7];
            }
        QRED(s[0]); QRED(s[1]); QRED(s[2]); QRED(s[3]);
        QRED(qq[0]); QRED(qq[1]); QRED(qq[2]); QRED(qq[3]);
        __syncthreads();                                   // W2 reads done before WS stores
#pragma unroll
        for (int i = 0; i < 4; i++) {
            STSF(SCA + (uint32_t)(4 * (rA + 8 * i) + wn) * 4, s[i]);
            STSF(WS + (uint32_t)(4 * (rA + 8 * i) + wn) * 4, qq[i]);
        }
        __syncthreads();
        float mu[4], iv[4];
#pragma unroll
        for (int i = 0; i < 4; i++) {
            float a0, a1, a2, a3, c0, c1, c2, c3;
            uint32_t bs = SCA + (uint32_t)(4 * (rA + 8 * i)) * 4;
            uint32_t bw = WS + (uint32_t)(4 * (rA + 8 * i)) * 4;
            LDSF(a0, bs); LDSF(a1, bs + 4); LDSF(a2, bs + 8); LDSF(a3, bs + 12);
            LDSF(c0, bw); LDSF(c1, bw + 4); LDSF(c2, bw + 8); LDSF(c3, bw + 12);
            mu[i] = (a0 + a1 + a2 + a3) * 0.0078125f;
            float var = (c0 + c1 + c2 + c3) * 0.0078125f - mu[i] * mu[i];
            iv[i] = rsqrtf(var + 1e-5f);
        }
#pragma unroll
        for (int rs = 0; rs < 2; rs++)
#pragma unroll
            for (int tn = 0; tn < 2; tn++) {
                float* e = acc + rs * 16 + tn * 8;
                int c = cb + 16 * tn + 2 * q;
                size_t ra = (size_t)(rA + 16 * rs), rb = ra + 8;
                *(float2*)(ob + ra * TSTRIDE + c) =
                    make_float2((e[0] - mu[2*rs]) * iv[2*rs], (e[1] - mu[2*rs]) * iv[2*rs]);
                *(float2*)(ob + rb * TSTRIDE + c) =
                    make_float2((e[2] - mu[2*rs+1]) * iv[2*rs+1], (e[3] - mu[2*rs+1]) * iv[2*rs+1]);
                *(float2*)(ob + ra * TSTRIDE + c + 8) =
                    make_float2((e[4] - mu[2*rs]) * iv[2*rs], (e[5] - mu[2*rs]) * iv[2*rs]);
                *(float2*)(ob + rb * TSTRIDE + c + 8) =
                    make_float2((e[6] - mu[2*rs+1]) * iv[2*rs+1], (e[7] - mu[2*rs+1]) * iv[2*rs+1]);
            }
    }
}

extern "C" void kernel_launch(void* const* d_in, const int* in_sizes, int n_in,
                              void* d_out, int out_size) {
    const float* x  = (const float*)d_in[0];
    const float* te = (const float*)d_in[1];
    const float* wq = (const float*)d_in[2];
    const float* bq = (const float*)d_in[3];
    const float* wk = (const float*)d_in[4];
    const float* bk = (const float*)d_in[5];
    const float* wv = (const float*)d_in[6];
    const float* bv = (const float*)d_in[7];
    const float* wo = (const float*)d_in[8];
    const float* bo = (const float*)d_in[9];
    const float* w1 = (const float*)d_in[10];
    const float* b1 = (const float*)d_in[11];
    const float* w2 = (const float*)d_in[12];
    const float* b2 = (const float*)d_in[13];
    float* out = (float*)d_out;

    prep_w<<<6, 256>>>(wk, wq, wv, wo, w1, w2);
    cudaFuncSetAttribute(fused_hmmaA, cudaFuncAttributeMaxDynamicSharedMemorySize, SMEM_TOT);
    fused_hmmaA<<<4096, THREADS, SMEM_TOT>>>(x, te, bq, bk, bv, bo, b1, b2, out);
}

// round 16
// speedup vs baseline: 1.1785x; 1.1621x over previous
#include <cuda_runtime.h>
#include <cuda_fp16.h>
#include <cstdint>

#define TSTRIDE 32768
#define THREADS 512

// smem byte offsets
#define BUF0 0u
#define BUF1 65536u
#define BUF2 131072u
#define WOFF 196608u      // Wv-hi staging -> V^T hi-only image -> LN scratch
#define SCOFF 229376u     // SCA: 512 floats
#define SMEM_TOT 231424

// Weight images (fp16): [wk, wq, wv] = hi 32KB | lo 32KB ; [wo, w1, w2] = hi only
__device__ __align__(16) unsigned char g_w[6][65536];

#define SWC(c, r7) ((uint32_t)(((((c) ^ (r7)) & 7) | ((c) & 8)) << 4))

// S-tile assignment (balanced bijection, from round 13)
#define SMTAB 0x1000212133213320ull
#define SNTAB 0x3321322131102000ull

__device__ __forceinline__ uint32_t smem_u32(const void* p) {
    uint32_t a;
    asm("{ .reg .u64 t; cvta.to.shared.u64 t, %1; cvt.u32.u64 %0, t; }" : "=r"(a) : "l"(p));
    return a;
}
__device__ __forceinline__ uint32_t f2h2(float a, float b) {   // lo=a, hi=b
    uint32_t r;
    asm("cvt.rn.f16x2.f32 %0, %1, %2;" : "=r"(r) : "f"(b), "f"(a));
    return r;
}
__device__ __forceinline__ float2 h2f2(uint32_t u) {
    __half2 h = *reinterpret_cast<__half2*>(&u);
    return __half22float2(h);
}
__device__ __forceinline__ void ldsm4(uint32_t* r, uint32_t a) {
    asm volatile("ldmatrix.sync.aligned.m8n8.x4.shared.b16 {%0,%1,%2,%3}, [%4];"
        : "=r"(r[0]), "=r"(r[1]), "=r"(r[2]), "=r"(r[3]) : "r"(a));
}
__device__ __forceinline__ void mma_f16(float* d, const uint32_t* a, uint32_t b0, uint32_t b1) {
    asm volatile("mma.sync.aligned.m16n8k16.row.col.f32.f16.f16.f32 "
        "{%0,%1,%2,%3}, {%4,%5,%6,%7}, {%8,%9}, {%0,%1,%2,%3};"
        : "+f"(d[0]), "+f"(d[1]), "+f"(d[2]), "+f"(d[3])
        : "r"(a[0]), "r"(a[1]), "r"(a[2]), "r"(a[3]), "r"(b0), "r"(b1));
}
#define STS32(a, v)  asm volatile("st.shared.b32 [%0], %1;" :: "r"(a), "r"(v) : "memory")
#define STS128(a, v0, v1, v2, v3) \
    asm volatile("st.shared.v4.b32 [%0], {%1,%2,%3,%4};" \
        :: "r"(a), "r"(v0), "r"(v1), "r"(v2), "r"(v3) : "memory")
#define LDS32(v, a)  asm volatile("ld.shared.b32 %0, [%1];" : "=r"(v) : "r"(a))
#define STSF(a, v)   asm volatile("st.shared.f32 [%0], %1;" :: "r"(a), "f"(v) : "memory")
#define LDSF(v, a)   asm volatile("ld.shared.f32 %0, [%1];" : "=f"(v) : "r"(a))
#define CP16(d, s) \
    asm volatile("cp.async.cg.shared.global [%0], [%1], 16;" :: "r"(d), "l"(s) : "memory")
#define CP_COMMIT  asm volatile("cp.async.commit_group;" ::: "memory")
#define CP_WAITALL asm volatile("cp.async.wait_group 0;" ::: "memory")
#define QRED(v) do { v += __shfl_xor_sync(~0u, v, 1); v += __shfl_xor_sync(~0u, v, 2); } while (0)

// ============ prep kernel ============
__global__ void prep_w(const float* __restrict__ wk, const float* __restrict__ wq,
                       const float* __restrict__ wv, const float* __restrict__ wo,
                       const float* __restrict__ w1, const float* __restrict__ w2) {
    const float* ws[6] = {wk, wq, wv, wo, w1, w2};
    const float* src = ws[blockIdx.x];
    unsigned char* dst = g_w[blockIdx.x];
    bool split = blockIdx.x < 3;
    for (int e = threadIdx.x; e < 16384; e += blockDim.x) {
        int f = e >> 7, k = e & 127;
        float val = src[k * 128 + f];            // W^T[f][k]
        __half h = __float2half(val);
        uint32_t off = (uint32_t)f * 256 + SWC(k >> 3, f & 7) + (uint32_t)(k & 7) * 2;
        *(__half*)(dst + off) = h;
        if (split) {
            __half l = __float2half(val - __half2float(h));
            *(__half*)(dst + 32768 + off) = l;
        }
    }
}

// ============ cp.async staging ============
__device__ __forceinline__ void cpa32(uint32_t dst, const unsigned char* src, int tid) {
#pragma unroll
    for (int i = 0; i < 4; i++)
        CP16(dst + (uint32_t)(tid * 16 + i * 8192), src + tid * 16 + i * 8192);
}
__device__ __forceinline__ void cpa64(uint32_t dst, const unsigned char* src, int tid) {
#pragma unroll
    for (int i = 0; i < 8; i++)
        CP16(dst + (uint32_t)(tid * 16 + i * 8192), src + tid * 16 + i * 8192);
}

// ============ GEMM cores: 32x32 warp tile, round-robin ============
// 3-pass chunk: 8 ldsm, 24 mma  (AhBh + AlBh + AhBl)
__device__ __forceinline__ void gchunk(uint32_t ahb, uint32_t alb, uint32_t bhb,
                                       uint32_t blb, float* acc,
                                       uint32_t ar0, uint32_t ar1,
                                       uint32_t br0, uint32_t br1, uint32_t csw) {
    uint32_t a0h[4], a0l[4], a1h[4], a1l[4];
    uint32_t b0h[4], b0l[4], b1h[4], b1l[4];
    ldsm4(a0h, ahb + ar0 + csw);
    ldsm4(a1h, ahb + ar1 + csw);
    ldsm4(b0h, bhb + br0 + csw);
    ldsm4(b1h, bhb + br1 + csw);
    ldsm4(a0l, alb + ar0 + csw);
    ldsm4(a1l, alb + ar1 + csw);
    ldsm4(b0l, blb + br0 + csw);
    ldsm4(b1l, blb + br1 + csw);
    mma_f16(acc+0,  a0h, b0h[0], b0h[2]); mma_f16(acc+4,  a0h, b0h[1], b0h[3]);
    mma_f16(acc+8,  a0h, b1h[0], b1h[2]); mma_f16(acc+12, a0h, b1h[1], b1h[3]);
    mma_f16(acc+16, a1h, b0h[0], b0h[2]); mma_f16(acc+20, a1h, b0h[1], b0h[3]);
    mma_f16(acc+24, a1h, b1h[0], b1h[2]); mma_f16(acc+28, a1h, b1h[1], b1h[3]);
    mma_f16(acc+0,  a0l, b0h[0], b0h[2]); mma_f16(acc+4,  a0l, b0h[1], b0h[3]);
    mma_f16(acc+8,  a0l, b1h[0], b1h[2]); mma_f16(acc+12, a0l, b1h[1], b1h[3]);
    mma_f16(acc+16, a1l, b0h[0], b0h[2]); mma_f16(acc+20, a1l, b0h[1], b0h[3]);
    mma_f16(acc+24, a1l, b1h[0], b1h[2]); mma_f16(acc+28, a1l, b1h[1], b1h[3]);
    mma_f16(acc+0,  a0h, b0l[0], b0l[2]); mma_f16(acc+4,  a0h, b0l[1], b0l[3]);
    mma_f16(acc+8,  a0h, b1l[0], b1l[2]); mma_f16(acc+12, a0h, b1l[1], b1l[3]);
    mma_f16(acc+16, a1h, b0l[0], b0l[2]); mma_f16(acc+20, a1h, b0l[1], b0l[3]);
    mma_f16(acc+24, a1h, b1l[0], b1l[2]); mma_f16(acc+28, a1h, b1l[1], b1l[3]);
}
// 2-pass chunk: 6 ldsm, 16 mma  (AhB + AlB, single B half)
__device__ __forceinline__ void gchunk2(uint32_t ahb, uint32_t alb, uint32_t bb,
                                        float* acc, uint32_t ar0, uint32_t ar1,
                                        uint32_t br0, uint32_t br1, uint32_t csw) {
    uint32_t a0h[4], a0l[4], a1h[4], a1l[4], b0[4], b1[4];
    ldsm4(a0h, ahb + ar0 + csw);
    ldsm4(a1h, ahb + ar1 + csw);
    ldsm4(b0, bb + br0 + csw);
    ldsm4(b1, bb + br1 + csw);
    ldsm4(a0l, alb + ar0 + csw);
    ldsm4(a1l, alb + ar1 + csw);
    mma_f16(acc+0,  a0h, b0[0], b0[2]); mma_f16(acc+4,  a0h, b0[1], b0[3]);
    mma_f16(acc+8,  a0h, b1[0], b1[2]); mma_f16(acc+12, a0h, b1[1], b1[3]);
    mma_f16(acc+16, a1h, b0[0], b0[2]); mma_f16(acc+20, a1h, b0[1], b0[3]);
    mma_f16(acc+24, a1h, b1[0], b1[2]); mma_f16(acc+28, a1h, b1[1], b1[3]);
    mma_f16(acc+0,  a0l, b0[0], b0[2]); mma_f16(acc+4,  a0l, b0[1], b0[3]);
    mma_f16(acc+8,  a0l, b1[0], b1[2]); mma_f16(acc+12, a0l, b1[1], b1[3]);
    mma_f16(acc+16, a1l, b0[0], b0[2]); mma_f16(acc+20, a1l, b0[1], b0[3]);
    mma_f16(acc+24, a1l, b1[0], b1[2]); mma_f16(acc+28, a1l, b1[1], b1[3]);
}

__device__ __forceinline__ void gfull(uint32_t ahb, uint32_t alb, uint32_t bhb,
                                      uint32_t blb, float* acc, int m0, int cb,
                                      int noff, int khalf) {
    const int rr = noff & 7;
    const uint32_t ar0 = (uint32_t)((m0 + noff) * 256), ar1 = ar0 + 4096;
    const uint32_t br0 = (uint32_t)((cb + noff) * 256), br1 = br0 + 4096;
#pragma unroll
    for (int j = 0; j < 8; j++)
        gchunk(ahb, alb, bhb, blb, acc, ar0, ar1, br0, br1, SWC(2 * j + khalf, rr));
}
__device__ __forceinline__ void gfull2(uint32_t ahb, uint32_t alb, uint32_t bb,
                                       float* acc, int m0, int cb, int noff, int khalf) {
    const int rr = noff & 7;
    const uint32_t ar0 = (uint32_t)((m0 + noff) * 256), ar1 = ar0 + 4096;
    const uint32_t br0 = (uint32_t)((cb + noff) * 256), br1 = br0 + 4096;
#pragma unroll
    for (int j = 0; j < 8; j++)
        gchunk2(ahb, alb, bb, acc, ar0, ar1, br0, br1, SWC(2 * j + khalf, rr));
}
__device__ __forceinline__ void gvar2(uint32_t ahb, uint32_t alb, uint32_t bb,
                                      float* acc, int m0, int cb, int noff, int khalf,
                                      int jmax) {
    const int rr = noff & 7;
    const uint32_t ar0 = (uint32_t)((m0 + noff) * 256), ar1 = ar0 + 4096;
    const uint32_t br0 = (uint32_t)((cb + noff) * 256), br1 = br0 + 4096;
#pragma unroll 2
    for (int j = 0; j < jmax; j++)
        gchunk2(ahb, alb, bb, acc, ar0, ar1, br0, br1, SWC(2 * j + khalf, rr));
}

__device__ __forceinline__ void zacc(float* acc) {
#pragma unroll
    for (int i = 0; i < 32; i++) acc[i] = 0.0f;
}

// store acc as hi/lo fp16 image
__device__ __forceinline__ void simg(uint32_t ibase, const float* acc, int m0, int cb,
                                     int g, int q) {
#pragma unroll
    for (int rs = 0; rs < 2; rs++)
#pragma unroll
        for (int tn = 0; tn < 2; tn++) {
            const float* e = acc + rs * 16 + tn * 8;
            int row = m0 + 16 * rs + g;
            uint32_t a0 = ibase + (uint32_t)(row * 256) + SWC((cb >> 3) + 2 * tn, g) + 4 * q;
            uint32_t a1 = ibase + (uint32_t)(row * 256) + SWC((cb >> 3) + 2 * tn + 1, g) + 4 * q;
            uint32_t h0 = f2h2(e[0], e[1]), h1 = f2h2(e[2], e[3]);
            float2 f0 = h2f2(h0), f1 = h2f2(h1);
            uint32_t l0 = f2h2(e[0] - f0.x, e[1] - f0.y);
            uint32_t l1 = f2h2(e[2] - f1.x, e[3] - f1.y);
            STS32(a0, h0);        STS32(a0 + 32768, l0);
            STS32(a0 + 2048, h1); STS32(a0 + 2048 + 32768, l1);
            uint32_t h2 = f2h2(e[4], e[5]), h3 = f2h2(e[6], e[7]);
            float2 f2 = h2f2(h2), f3 = h2f2(h3);
            uint32_t l2 = f2h2(e[4] - f2.x, e[5] - f2.y);
            uint32_t l3 = f2h2(e[6] - f3.x, e[7] - f3.y);
            STS32(a1, h2);        STS32(a1 + 32768, l2);
            STS32(a1 + 2048, h3); STS32(a1 + 2048 + 32768, l3);
        }
}
// store acc as hi-only fp16 image (32KB region)
__device__ __forceinline__ void simgh(uint32_t ibase, const float* acc, int m0, int cb,
                                      int g, int q) {
#pragma unroll
    for (int rs = 0; rs < 2; rs++)
#pragma unroll
        for (int tn = 0; tn < 2; tn++) {
            const float* e = acc + rs * 16 + tn * 8;
            int row = m0 + 16 * rs + g;
            uint32_t a0 = ibase + (uint32_t)(row * 256) + SWC((cb >> 3) + 2 * tn, g) + 4 * q;
            uint32_t a1 = ibase + (uint32_t)(row * 256) + SWC((cb >> 3) + 2 * tn + 1, g) + 4 * q;
            STS32(a0, f2h2(e[0], e[1]));
            STS32(a0 + 2048, f2h2(e[2], e[3]));
            STS32(a1, f2h2(e[4], e[5]));
            STS32(a1 + 2048, f2h2(e[6], e[7]));
        }
}

__device__ __forceinline__ void biasc(float* acc, const float* __restrict__ bias,
                                      int cb, int q) {
#pragma unroll
    for (int rs = 0; rs < 2; rs++)
#pragma unroll
        for (int tn = 0; tn < 2; tn++) {
            float* e = acc + rs * 16 + tn * 8;
            float2 b0 = __ldg((const float2*)(bias + cb + 16 * tn + 2 * q));
            float2 b1 = __ldg((const float2*)(bias + cb + 16 * tn + 8 + 2 * q));
            e[0] += b0.x; e[1] += b0.y; e[2] += b0.x; e[3] += b0.y;
            e[4] += b1.x; e[5] += b1.y; e[6] += b1.x; e[7] += b1.y;
        }
}

// ============ main kernel ============
__global__ void __launch_bounds__(THREADS, 1)
fused_hmmaB(const float* __restrict__ x, const float* __restrict__ te,
            const float* __restrict__ bq, const float* __restrict__ bk,
            const float* __restrict__ bv, const float* __restrict__ bo,
            const float* __restrict__ b1, const float* __restrict__ b2,
            float* __restrict__ out) {
    extern __shared__ char smc[];
    const uint32_t sb = smem_u32(smc);
    const uint32_t B0 = sb + BUF0, B1 = sb + BUF1, B2 = sb + BUF2, W = sb + WOFF;
    const uint32_t SCA = sb + SCOFF;
    const uint32_t WS = W;                // LN sumsq scratch (V^T dead by LN time)

    const int tid = threadIdx.x, lane = tid & 31, w = tid >> 5;
    const int wm = w >> 2, wn = w & 3;
    const int m0 = 32 * wm, cb = 32 * wn;
    const int g = lane >> 2, q = lane & 3;
    const int noff = ((lane >> 3) & 1) * 8 + (lane & 7);
    const int khalf = lane >> 4;
    const int rA = m0 + g;

    const int bn = blockIdx.x, b = bn >> 8, n = bn & 255;
    const float* xb  = x  + (size_t)b * 128 * TSTRIDE + (size_t)n * 128;
    const float* teb = te + (size_t)b * 128 * TSTRIDE + (size_t)n * 128;
    float* ob = out + (size_t)b * 128 * TSTRIDE + (size_t)n * 128;

    // G0: Wk -> B2, Wq -> B1 (both h+l)
    cpa64(B2, g_w[0], tid);
    cpa64(B1, g_w[1], tid);
    CP_COMMIT;

    // ---- build X = x+te hi/lo fp16 image -> BUF0 ----
    {
        int row = tid >> 2, quarter = tid & 3;
        const float4* xr = (const float4*)(xb  + (size_t)row * TSTRIDE + 32 * quarter);
        const float4* tr = (const float4*)(teb + (size_t)row * TSTRIDE + 32 * quarter);
#pragma unroll
        for (int ci = 0; ci < 4; ci++) {
            float4 a = xr[2*ci], c = tr[2*ci], a2 = xr[2*ci+1], c2 = tr[2*ci+1];
            float v0 = a.x + c.x, v1 = a.y + c.y, v2 = a.z + c.z, v3 = a.w + c.w;
            float v4 = a2.x + c2.x, v5 = a2.y + c2.y, v6 = a2.z + c2.z, v7 = a2.w + c2.w;
            uint32_t h0 = f2h2(v0, v1), h1 = f2h2(v2, v3);
            uint32_t h2 = f2h2(v4, v5), h3 = f2h2(v6, v7);
            float2 e0 = h2f2(h0), e1 = h2f2(h1), e2 = h2f2(h2), e3 = h2f2(h3);
            uint32_t l0 = f2h2(v0 - e0.x, v1 - e0.y), l1 = f2h2(v2 - e1.x, v3 - e1.y);
            uint32_t l2 = f2h2(v4 - e2.x, v5 - e2.y), l3 = f2h2(v6 - e3.x, v7 - e3.y);
            uint32_t addr = B0 + (uint32_t)row * 256 + SWC(4 * quarter + ci, row & 7);
            STS128(addr, h0, h1, h2, h3);
            STS128(addr + 32768, l0, l1, l2, l3);
        }
    }
    CP_WAITALL;
    __syncthreads();

    float acc[32];

    // ==== P1: K = X @ Wk (3-pass) -> B2 ====
    zacc(acc);
    gfull(B0, B0 + 32768, B2, B2 + 32768, acc, m0, cb, noff, khalf);
    biasc(acc, bk, cb, q);
    __syncthreads();
    simg(B2, acc, m0, cb, g, q);

    // ==== P2: Q = X @ Wq (3-pass, Wq in B1) -> B1 ====
    zacc(acc);
    gfull(B0, B0 + 32768, B1, B1 + 32768, acc, m0, cb, noff, khalf);
    biasc(acc, bq, cb, q);
    __syncthreads();                       // Wq + X-lo reads done
    cpa32(W, g_w[2], tid);                 // Wv-hi -> W
    cpa32(B0 + 32768, g_w[2] + 32768, tid);// Wv-lo -> X-lo region (X-lo dead)
    CP_COMMIT;
    simg(B1, acc, m0, cb, g, q);           // Q image (over Wq)
    CP_WAITALL;
    __syncthreads();

    // ==== P3: V^T = Wv @ Xh (2-pass: Ah=W, Al=B0lo, B=B0hi) -> W (hi-only) ====
    zacc(acc);
    gfull2(W, B0 + 32768, B0, acc, m0, cb, noff, khalf);
    {
        float bv0 = __ldg(bv + rA), bv1 = __ldg(bv + rA + 8);
        float bv2 = __ldg(bv + rA + 16), bv3 = __ldg(bv + rA + 24);
#pragma unroll
        for (int tn = 0; tn < 2; tn++) {
#pragma unroll
            for (int j = 0; j < 4; j++) {
                acc[8*tn + j] += (j < 2) ? bv0 : bv1;
                acc[8*tn + 4 + j] += (j < 2) ? bv0 : bv1;
                acc[16 + 8*tn + j] += (j < 2) ? bv2 : bv3;
                acc[16 + 8*tn + 4 + j] += (j < 2) ? bv2 : bv3;
            }
        }
    }
    __syncthreads();                       // Wv + X reads done
    simgh(W, acc, m0, cb, g, q);           // V^T hi-only image (over Wv-hi)

    // ==== P4: S (assigned tile, 3-pass) -> softmax -> P -> B0 ====
    {
        const int sm = (int)((SMTAB >> (4 * w)) & 7);
        const int sn = (int)((SNTAB >> (4 * w)) & 7);
        const bool masked = sn > sm;
        const int sm0 = 32 * sm, scb = 32 * sn;
        const int rS = sm0 + g;
        zacc(acc);
        if (!masked)
            gfull(B1, B1 + 32768, B2, B2 + 32768, acc, sm0, scb, noff, khalf);
        float s[4] = {0, 0, 0, 0};
        if (!masked) {
#pragma unroll
            for (int rs = 0; rs < 2; rs++)
#pragma unroll
                for (int tn = 0; tn < 2; tn++) {
                    float* e = acc + rs * 16 + tn * 8;
                    int ra = rS + 16 * rs, rb = ra + 8;
                    int c0 = scb + 16 * tn + 2 * q;
                    int c1 = c0 + 8;
                    float p0 = (c0     <= ra) ? __expf(e[0] * 0.25f) : 0.0f;
                    float p1 = (c0 + 1 <= ra) ? __expf(e[1] * 0.25f) : 0.0f;
                    float p2 = (c0     <= rb) ? __expf(e[2] * 0.25f) : 0.0f;
                    float p3 = (c0 + 1 <= rb) ? __expf(e[3] * 0.25f) : 0.0f;
                    float p4 = (c1     <= ra) ? __expf(e[4] * 0.25f) : 0.0f;
                    float p5 = (c1 + 1 <= ra) ? __expf(e[5] * 0.25f) : 0.0f;
                    float p6 = (c1     <= rb) ? __expf(e[6] * 0.25f) : 0.0f;
                    float p7 = (c1 + 1 <= rb) ? __expf(e[7] * 0.25f) : 0.0f;
                    e[0]=p0; e[1]=p1; e[2]=p2; e[3]=p3; e[4]=p4; e[5]=p5; e[6]=p6; e[7]=p7;
                    s[2*rs]   += p0 + p1 + p4 + p5;
                    s[2*rs+1] += p2 + p3 + p6 + p7;
                }
        }
        QRED(s[0]); QRED(s[1]); QRED(s[2]); QRED(s[3]);
        STSF(SCA + (uint32_t)(4 * rS + sn) * 4, s[0]);
        STSF(SCA + (uint32_t)(4 * (rS + 8) + sn) * 4, s[1]);
        STSF(SCA + (uint32_t)(4 * (rS + 16) + sn) * 4, s[2]);
        STSF(SCA + (uint32_t)(4 * (rS + 24) + sn) * 4, s[3]);
        __syncthreads();                   // K,Q reads + sums done
        cpa32(B2, g_w[3], tid); CP_COMMIT; // Wo-hi -> B2 (K dead)
        if (!masked) {
            float inv[4];
#pragma unroll
            for (int i = 0; i < 4; i++) {
                float a0, a1, a2, a3;
                uint32_t base = SCA + (uint32_t)(4 * (rS + 8 * i)) * 4;
                LDSF(a0, base); LDSF(a1, base + 4); LDSF(a2, base + 8); LDSF(a3, base + 12);
                inv[i] = 1.0f / (a0 + a1 + a2 + a3);
            }
#pragma unroll
            for (int rs = 0; rs < 2; rs++)
#pragma unroll
                for (int tn = 0; tn < 2; tn++) {
                    float* e = acc + rs * 16 + tn * 8;
                    e[0] *= inv[2*rs]; e[1] *= inv[2*rs];
                    e[2] *= inv[2*rs+1]; e[3] *= inv[2*rs+1];
                    e[4] *= inv[2*rs]; e[5] *= inv[2*rs];
                    e[6] *= inv[2*rs+1]; e[7] *= inv[2*rs+1];
                }
            simg(B0, acc, sm0, scb, g, q); // P image (X dead)
        }
        __syncthreads();
    }

    // ==== P5: AO = P @ V (2-pass, B = V^T hi in W; jmax = 2wm+2) -> B1 ====
    zacc(acc);
    gvar2(B0, B0 + 32768, W, acc, m0, cb, noff, khalf, 2 * wm + 2);
    __syncthreads();                       // P + V reads done
    simg(B1, acc, m0, cb, g, q);           // AO image (Q dead)
    CP_WAITALL;
    __syncthreads();                       // AO + Wo visible

    // ==== P6: U = LN(AO @ Wo + bo + (x+te)) -> B0 ====
    zacc(acc);
    gfull2(B1, B1 + 32768, B2, acc, m0, cb, noff, khalf);
    biasc(acc, bo, cb, q);
#pragma unroll
    for (int rs = 0; rs < 2; rs++)
#pragma unroll
        for (int tn = 0; tn < 2; tn++) {
            float* e = acc + rs * 16 + tn * 8;
            int c = cb + 16 * tn + 2 * q;
            size_t ra = (size_t)(rA + 16 * rs), rb = ra + 8;
            float2 xa = *(const float2*)(xb + ra * TSTRIDE + c);
            float2 ta = *(const float2*)(teb + ra * TSTRIDE + c);
            e[0] += xa.x + ta.x; e[1] += xa.y + ta.y;
            float2 xc = *(const float2*)(xb + rb * TSTRIDE + c);
            float2 tc = *(const float2*)(teb + rb * TSTRIDE + c);
            e[2] += xc.x + tc.x; e[3] += xc.y + tc.y;
            float2 xe = *(const float2*)(xb + ra * TSTRIDE + c + 8);
            float2 tee = *(const float2*)(teb + ra * TSTRIDE + c + 8);
            e[4] += xe.x + tee.x; e[5] += xe.y + tee.y;
            float2 xg = *(const float2*)(xb + rb * TSTRIDE + c + 8);
            float2 tg = *(const float2*)(teb + rb * TSTRIDE + c + 8);
            e[6] += xg.x + tg.x; e[7] += xg.y + tg.y;
        }
    {   // 1-round LN
        float s[4] = {0,0,0,0}, qq[4] = {0,0,0,0};
#pragma unroll
        for (int rs = 0; rs < 2; rs++)
#pragma unroll
            for (int tn = 0; tn < 2; tn++) {
                float* e = acc + rs * 16 + tn * 8;
                s[2*rs]   += e[0] + e[1] + e[4] + e[5];
                s[2*rs+1] += e[2] + e[3] + e[6] + e[7];
                qq[2*rs]   += e[0]*e[0] + e[1]*e[1] + e[4]*e[4] + e[5]*e[5];
                qq[2*rs+1] += e[2]*e[2] + e[3]*e[3] + e[6]*e[6] + e[7]*e[7];
            }
        QRED(s[0]); QRED(s[1]); QRED(s[2]); QRED(s[3]);
        QRED(qq[0]); QRED(qq[1]); QRED(qq[2]); QRED(qq[3]);
#pragma unroll
        for (int i = 0; i < 4; i++) {
            STSF(SCA + (uint32_t)(4 * (rA + 8 * i) + wn) * 4, s[i]);
            STSF(WS + (uint32_t)(4 * (rA + 8 * i) + wn) * 4, qq[i]);
        }
        __syncthreads();                   // also retires Wo reads
        float mu[4], iv[4];
#pragma unroll
        for (int i = 0; i < 4; i++) {
            float a0, a1, a2, a3, c0, c1, c2, c3;
            uint32_t bs = SCA + (uint32_t)(4 * (rA + 8 * i)) * 4;
            uint32_t bw = WS + (uint32_t)(4 * (rA + 8 * i)) * 4;
            LDSF(a0, bs); LDSF(a1, bs + 4); LDSF(a2, bs + 8); LDSF(a3, bs + 12);
            LDSF(c0, bw); LDSF(c1, bw + 4); LDSF(c2, bw + 8); LDSF(c3, bw + 12);
            mu[i] = (a0 + a1 + a2 + a3) * 0.0078125f;
            float var = (c0 + c1 + c2 + c3) * 0.0078125f - mu[i] * mu[i];
            iv[i] = rsqrtf(var + 1e-5f);
        }
#pragma unroll
        for (int rs = 0; rs < 2; rs++)
#pragma unroll
            for (int tn = 0; tn < 2; tn++) {
                float* e = acc + rs * 16 + tn * 8;
                e[0] = (e[0] - mu[2*rs]) * iv[2*rs];   e[1] = (e[1] - mu[2*rs]) * iv[2*rs];
                e[4] = (e[4] - mu[2*rs]) * iv[2*rs];   e[5] = (e[5] - mu[2*rs]) * iv[2*rs];
                e[2] = (e[2] - mu[2*rs+1]) * iv[2*rs+1]; e[3] = (e[3] - mu[2*rs+1]) * iv[2*rs+1];
                e[6] = (e[6] - mu[2*rs+1]) * iv[2*rs+1]; e[7] = (e[7] - mu[2*rs+1]) * iv[2*rs+1];
            }
    }
    cpa32(B2, g_w[4], tid); CP_COMMIT;     // W1 -> B2 (Wo dead)
    simg(B0, acc, m0, cb, g, q);           // U image (P dead)
    CP_WAITALL;
    __syncthreads();

    // ==== P7: H = relu(U @ W1 + b1) (2-pass) -> B1 ====
    zacc(acc);
    gfull2(B0, B0 + 32768, B2, acc, m0, cb, noff, khalf);
    biasc(acc, b1, cb, q);
#pragma unroll
    for (int i = 0; i < 32; i++) acc[i] = fmaxf(acc[i], 0.0f);
    __syncthreads();                       // W1 reads done
    cpa32(B2, g_w[5], tid); CP_COMMIT;     // W2 -> B2
    simg(B1, acc, m0, cb, g, q);           // H image (AO dead)
    CP_WAITALL;
    __syncthreads();

    // ==== P8: out = LN(H @ W2 + b2 + U) (2-pass) -> gmem ====
    zacc(acc);
    gfull2(B1, B1 + 32768, B2, acc, m0, cb, noff, khalf);
    biasc(acc, b2, cb, q);
#pragma unroll
    for (int rs = 0; rs < 2; rs++)
#pragma unroll
        for (int tn = 0; tn < 2; tn++) {   // + U residual from B0 (h+l)
            float* e = acc + rs * 16 + tn * 8;
            int row = m0 + 16 * rs + g;
            uint32_t a0 = B0 + (uint32_t)(row * 256) + SWC((cb >> 3) + 2 * tn, g) + 4 * q;
            uint32_t a1 = B0 + (uint32_t)(row * 256) + SWC((cb >> 3) + 2 * tn + 1, g) + 4 * q;
            uint32_t h, l;
            LDS32(h, a0); LDS32(l, a0 + 32768);
            float2 hf = h2f2(h), lf = h2f2(l);
            e[0] += hf.x + lf.x; e[1] += hf.y + lf.y;
            LDS32(h, a0 + 2048); LDS32(l, a0 + 2048 + 32768);
            hf = h2f2(h); lf = h2f2(l);
            e[2] += hf.x + lf.x; e[3] += hf.y + lf.y;
            LDS32(h, a1); LDS32(l, a1 + 32768);
            hf = h2f2(h); lf = h2f2(l);
            e[4] += hf.x + lf.x; e[5] += hf.y + lf.y;
            LDS32(h, a1 + 2048); LDS32(l, a1 + 2048 + 32768);
            hf = h2f2(h); lf = h2f2(l);
            e[6] += hf.x + lf.x; e[7] += hf.y + lf.y;
        }
    {   // 1-round final LN
        float s[4] = {0,0,0,0}, qq[4] = {0,0,0,0};
#pragma unroll
        for (int rs = 0; rs < 2; rs++)
#pragma unroll
            for (int tn = 0; tn < 2; tn++) {
                float* e = acc + rs * 16 + tn * 8;
                s[2*rs]   += e[0] + e[1] + e[4] + e[5];
                s[2*rs+1] += e[2] + e[3] + e[6] + e[7];
                qq[2*rs]   += e[0]*e[0] + e[1]*e[1] + e[4]*e[4] + e[5]*e[5];
                qq[2*rs+1] += e[2]*e[2] + e[3]*e[3] + e[6]*e[6] + e[7]*e[7];
            }
        QRED(s[0]); QRED(s[1]); QRED(s[2]); QRED(s[3]);
        QRED(qq[0]); QRED(qq[1]); QRED(qq[2]); QRED(qq[3]);
#pragma unroll
        for (int i = 0; i < 4; i++) {
            STSF(SCA + (uint32_t)(4 * (rA + 8 * i) + wn) * 4, s[i]);
            STSF(WS + (uint32_t)(4 * (rA + 8 * i) + wn) * 4, qq[i]);
        }
        __syncthreads();
        float mu[4], iv[4];
#pragma unroll
        for (int i = 0; i < 4; i++) {
            float a0, a1, a2, a3, c0, c1, c2, c3;
            uint32_t bs = SCA + (uint32_t)(4 * (rA + 8 * i)) * 4;
            uint32_t bw = WS + (uint32_t)(4 * (rA + 8 * i)) * 4;
            LDSF(a0, bs); LDSF(a1, bs + 4); LDSF(a2, bs + 8); LDSF(a3, bs + 12);
            LDSF(c0, bw); LDSF(c1, bw + 4); LDSF(c2, bw + 8); LDSF(c3, bw + 12);
            mu[i] = (a0 + a1 + a2 + a3) * 0.0078125f;
            float var = (c0 + c1 + c2 + c3) * 0.0078125f - mu[i] * mu[i];
            iv[i] = rsqrtf(var + 1e-5f);
        }
#pragma unroll
        for (int rs = 0; rs < 2; rs++)
#pragma unroll
            for (int tn = 0; tn < 2; tn++) {
                float* e = acc + rs * 16 + tn * 8;
                int c = cb + 16 * tn + 2 * q;
                size_t ra = (size_t)(rA + 16 * rs), rb = ra + 8;
                *(float2*)(ob + ra * TSTRIDE + c) =
                    make_float2((e[0] - mu[2*rs]) * iv[2*rs], (e[1] - mu[2*rs]) * iv[2*rs]);
                *(float2*)(ob + rb * TSTRIDE + c) =
                    make_float2((e[2] - mu[2*rs+1]) * iv[2*rs+1], (e[3] - mu[2*rs+1]) * iv[2*rs+1]);
                *(float2*)(ob + ra * TSTRIDE + c + 8) =
                    make_float2((e[4] - mu[2*rs]) * iv[2*rs], (e[5] - mu[2*rs]) * iv[2*rs]);
                *(float2*)(ob + rb * TSTRIDE + c + 8) =
                    make_float2((e[6] - mu[2*rs+1]) * iv[2*rs+1], (e[7] - mu[2*rs+1]) * iv[2*rs+1]);
            }
    }
}

extern "C" void kernel_launch(void* const* d_in, const int* in_sizes, int n_in,
                              void* d_out, int out_size) {
    const float* x  = (const float*)d_in[0];
    const float* te = (const float*)d_in[1];
    const float* wq = (const float*)d_in[2];
    const float* bq = (const float*)d_in[3];
    const float* wk = (const float*)d_in[4];
    const float* bk = (const float*)d_in[5];
    const float* wv = (const float*)d_in[6];
    const float* bv = (const float*)d_in[7];
    const float* wo = (const float*)d_in[8];
    const float* bo = (const float*)d_in[9];
    const float* w1 = (const float*)d_in[10];
    const float* b1 = (const float*)d_in[11];
    const float* w2 = (const float*)d_in[12];
    const float* b2 = (const float*)d_in[13];
    float* out = (float*)d_out;

    prep_w<<<6, 256>>>(wk, wq, wv, wo, w1, w2);
    cudaFuncSetAttribute(fused_hmmaB, cudaFuncAttributeMaxDynamicSharedMemorySize, SMEM_TOT);
    fused_hmmaB<<<4096, THREADS, SMEM_TOT>>>(x, te, bq, bk, bv, bo, b1, b2, out);
}

// round 17
// speedup vs baseline: 1.2468x; 1.0579x over previous
#include <cuda_runtime.h>
#include <cuda_fp16.h>
#include <cstdint>

#define TSTRIDE 32768
#define THREADS 512

// smem byte offsets
#define BUF0 0u
#define BUF1 65536u
#define BUF2 131072u
#define WOFF 196608u      // Wv-hi staging -> V^T hi-only image -> LN scratch
#define SCOFF 229376u     // SCA: 512 floats
#define SMEM_TOT 231424

// Weight images (fp16): [wk, wq, wv] = hi 32KB | lo 32KB ; [wo, w1, w2] = hi only
__device__ __align__(16) unsigned char g_w[6][65536];

#define SWC(c, r7) ((uint32_t)(((((c) ^ (r7)) & 7) | ((c) & 8)) << 4))

// S-tile assignment (balanced bijection)
#define SMTAB 0x1000212133213320ull
#define SNTAB 0x3321322131102000ull

__device__ __forceinline__ uint32_t smem_u32(const void* p) {
    uint32_t a;
    asm("{ .reg .u64 t; cvta.to.shared.u64 t, %1; cvt.u32.u64 %0, t; }" : "=r"(a) : "l"(p));
    return a;
}
__device__ __forceinline__ uint32_t f2h2(float a, float b) {   // lo=a, hi=b
    uint32_t r;
    asm("cvt.rn.f16x2.f32 %0, %1, %2;" : "=r"(r) : "f"(b), "f"(a));
    return r;
}
__device__ __forceinline__ float2 h2f2(uint32_t u) {
    __half2 h = *reinterpret_cast<__half2*>(&u);
    return __half22float2(h);
}
__device__ __forceinline__ void ldsm4(uint32_t* r, uint32_t a) {
    asm volatile("ldmatrix.sync.aligned.m8n8.x4.shared.b16 {%0,%1,%2,%3}, [%4];"
        : "=r"(r[0]), "=r"(r[1]), "=r"(r[2]), "=r"(r[3]) : "r"(a));
}
__device__ __forceinline__ void mma_f16(float* d, const uint32_t* a, uint32_t b0, uint32_t b1) {
    asm volatile("mma.sync.aligned.m16n8k16.row.col.f32.f16.f16.f32 "
        "{%0,%1,%2,%3}, {%4,%5,%6,%7}, {%8,%9}, {%0,%1,%2,%3};"
        : "+f"(d[0]), "+f"(d[1]), "+f"(d[2]), "+f"(d[3])
        : "r"(a[0]), "r"(a[1]), "r"(a[2]), "r"(a[3]), "r"(b0), "r"(b1));
}
#define STS32(a, v)  asm volatile("st.shared.b32 [%0], %1;" :: "r"(a), "r"(v) : "memory")
#define STS128(a, v0, v1, v2, v3) \
    asm volatile("st.shared.v4.b32 [%0], {%1,%2,%3,%4};" \
        :: "r"(a), "r"(v0), "r"(v1), "r"(v2), "r"(v3) : "memory")
#define LDS32(v, a)  asm volatile("ld.shared.b32 %0, [%1];" : "=r"(v) : "r"(a))
#define STSF(a, v)   asm volatile("st.shared.f32 [%0], %1;" :: "r"(a), "f"(v) : "memory")
#define LDSF(v, a)   asm volatile("ld.shared.f32 %0, [%1];" : "=f"(v) : "r"(a))
#define CP16(d, s) \
    asm volatile("cp.async.cg.shared.global [%0], [%1], 16;" :: "r"(d), "l"(s) : "memory")
#define CP_COMMIT  asm volatile("cp.async.commit_group;" ::: "memory")
#define CP_WAITALL asm volatile("cp.async.wait_group 0;" ::: "memory")
#define QRED(v) do { v += __shfl_xor_sync(~0u, v, 1); v += __shfl_xor_sync(~0u, v, 2); } while (0)

// ============ prep kernel ============
__global__ void prep_w(const float* __restrict__ wk, const float* __restrict__ wq,
                       const float* __restrict__ wv, const float* __restrict__ wo,
                       const float* __restrict__ w1, const float* __restrict__ w2) {
    const float* ws[6] = {wk, wq, wv, wo, w1, w2};
    const float* src = ws[blockIdx.x];
    unsigned char* dst = g_w[blockIdx.x];
    bool split = blockIdx.x < 3;
    for (int e = threadIdx.x; e < 16384; e += blockDim.x) {
        int f = e >> 7, k = e & 127;
        float val = src[k * 128 + f];            // W^T[f][k]
        __half h = __float2half(val);
        uint32_t off = (uint32_t)f * 256 + SWC(k >> 3, f & 7) + (uint32_t)(k & 7) * 2;
        *(__half*)(dst + off) = h;
        if (split) {
            __half l = __float2half(val - __half2float(h));
            *(__half*)(dst + 32768 + off) = l;
        }
    }
}

// ============ cp.async staging ============
__device__ __forceinline__ void cpa32(uint32_t dst, const unsigned char* src, int tid) {
#pragma unroll
    for (int i = 0; i < 4; i++)
        CP16(dst + (uint32_t)(tid * 16 + i * 8192), src + tid * 16 + i * 8192);
}
__device__ __forceinline__ void cpa64(uint32_t dst, const unsigned char* src, int tid) {
#pragma unroll
    for (int i = 0; i < 8; i++)
        CP16(dst + (uint32_t)(tid * 16 + i * 8192), src + tid * 16 + i * 8192);
}

// ============ GEMM cores: 32x32 warp tile, round-robin ============
// 3-pass chunk: 8 ldsm, 24 mma
__device__ __forceinline__ void gchunk(uint32_t ahb, uint32_t alb, uint32_t bhb,
                                       uint32_t blb, float* acc,
                                       uint32_t ar0, uint32_t ar1,
                                       uint32_t br0, uint32_t br1, uint32_t csw) {
    uint32_t a0h[4], a0l[4], a1h[4], a1l[4];
    uint32_t b0h[4], b0l[4], b1h[4], b1l[4];
    ldsm4(a0h, ahb + ar0 + csw);
    ldsm4(a1h, ahb + ar1 + csw);
    ldsm4(b0h, bhb + br0 + csw);
    ldsm4(b1h, bhb + br1 + csw);
    ldsm4(a0l, alb + ar0 + csw);
    ldsm4(a1l, alb + ar1 + csw);
    ldsm4(b0l, blb + br0 + csw);
    ldsm4(b1l, blb + br1 + csw);
    mma_f16(acc+0,  a0h, b0h[0], b0h[2]); mma_f16(acc+4,  a0h, b0h[1], b0h[3]);
    mma_f16(acc+8,  a0h, b1h[0], b1h[2]); mma_f16(acc+12, a0h, b1h[1], b1h[3]);
    mma_f16(acc+16, a1h, b0h[0], b0h[2]); mma_f16(acc+20, a1h, b0h[1], b0h[3]);
    mma_f16(acc+24, a1h, b1h[0], b1h[2]); mma_f16(acc+28, a1h, b1h[1], b1h[3]);
    mma_f16(acc+0,  a0l, b0h[0], b0h[2]); mma_f16(acc+4,  a0l, b0h[1], b0h[3]);
    mma_f16(acc+8,  a0l, b1h[0], b1h[2]); mma_f16(acc+12, a0l, b1h[1], b1h[3]);
    mma_f16(acc+16, a1l, b0h[0], b0h[2]); mma_f16(acc+20, a1l, b0h[1], b0h[3]);
    mma_f16(acc+24, a1l, b1h[0], b1h[2]); mma_f16(acc+28, a1l, b1h[1], b1h[3]);
    mma_f16(acc+0,  a0h, b0l[0], b0l[2]); mma_f16(acc+4,  a0h, b0l[1], b0l[3]);
    mma_f16(acc+8,  a0h, b1l[0], b1l[2]); mma_f16(acc+12, a0h, b1l[1], b1l[3]);
    mma_f16(acc+16, a1h, b0l[0], b0l[2]); mma_f16(acc+20, a1h, b0l[1], b0l[3]);
    mma_f16(acc+24, a1h, b1l[0], b1l[2]); mma_f16(acc+28, a1h, b1l[1], b1l[3]);
}
// 2-pass chunk: 6 ldsm, 16 mma
__device__ __forceinline__ void gchunk2(uint32_t ahb, uint32_t alb, uint32_t bb,
                                        float* acc, uint32_t ar0, uint32_t ar1,
                                        uint32_t br0, uint32_t br1, uint32_t csw) {
    uint32_t a0h[4], a0l[4], a1h[4], a1l[4], b0[4], b1[4];
    ldsm4(a0h, ahb + ar0 + csw);
    ldsm4(a1h, ahb + ar1 + csw);
    ldsm4(b0, bb + br0 + csw);
    ldsm4(b1, bb + br1 + csw);
    ldsm4(a0l, alb + ar0 + csw);
    ldsm4(a1l, alb + ar1 + csw);
    mma_f16(acc+0,  a0h, b0[0], b0[2]); mma_f16(acc+4,  a0h, b0[1], b0[3]);
    mma_f16(acc+8,  a0h, b1[0], b1[2]); mma_f16(acc+12, a0h, b1[1], b1[3]);
    mma_f16(acc+16, a1h, b0[0], b0[2]); mma_f16(acc+20, a1h, b0[1], b0[3]);
    mma_f16(acc+24, a1h, b1[0], b1[2]); mma_f16(acc+28, a1h, b1[1], b1[3]);
    mma_f16(acc+0,  a0l, b0[0], b0[2]); mma_f16(acc+4,  a0l, b0[1], b0[3]);
    mma_f16(acc+8,  a0l, b1[0], b1[2]); mma_f16(acc+12, a0l, b1[1], b1[3]);
    mma_f16(acc+16, a1l, b0[0], b0[2]); mma_f16(acc+20, a1l, b0[1], b0[3]);
    mma_f16(acc+24, a1l, b1[0], b1[2]); mma_f16(acc+28, a1l, b1[1], b1[3]);
}
// 1-pass chunk: 4 ldsm, 8 mma
__device__ __forceinline__ void gchunk1(uint32_t ab, uint32_t bb, float* acc,
                                        uint32_t ar0, uint32_t ar1,
                                        uint32_t br0, uint32_t br1, uint32_t csw) {
    uint32_t a0[4], a1[4], b0[4], b1[4];
    ldsm4(a0, ab + ar0 + csw);
    ldsm4(a1, ab + ar1 + csw);
    ldsm4(b0, bb + br0 + csw);
    ldsm4(b1, bb + br1 + csw);
    mma_f16(acc+0,  a0, b0[0], b0[2]); mma_f16(acc+4,  a0, b0[1], b0[3]);
    mma_f16(acc+8,  a0, b1[0], b1[2]); mma_f16(acc+12, a0, b1[1], b1[3]);
    mma_f16(acc+16, a1, b0[0], b0[2]); mma_f16(acc+20, a1, b0[1], b0[3]);
    mma_f16(acc+24, a1, b1[0], b1[2]); mma_f16(acc+28, a1, b1[1], b1[3]);
}

__device__ __forceinline__ void gfull(uint32_t ahb, uint32_t alb, uint32_t bhb,
                                      uint32_t blb, float* acc, int m0, int cb,
                                      int noff, int khalf) {
    const int rr = noff & 7;
    const uint32_t ar0 = (uint32_t)((m0 + noff) * 256), ar1 = ar0 + 4096;
    const uint32_t br0 = (uint32_t)((cb + noff) * 256), br1 = br0 + 4096;
#pragma unroll
    for (int j = 0; j < 8; j++)
        gchunk(ahb, alb, bhb, blb, acc, ar0, ar1, br0, br1, SWC(2 * j + khalf, rr));
}
__device__ __forceinline__ void gfull2(uint32_t ahb, uint32_t alb, uint32_t bb,
                                       float* acc, int m0, int cb, int noff, int khalf) {
    const int rr = noff & 7;
    const uint32_t ar0 = (uint32_t)((m0 + noff) * 256), ar1 = ar0 + 4096;
    const uint32_t br0 = (uint32_t)((cb + noff) * 256), br1 = br0 + 4096;
#pragma unroll
    for (int j = 0; j < 8; j++)
        gchunk2(ahb, alb, bb, acc, ar0, ar1, br0, br1, SWC(2 * j + khalf, rr));
}
__device__ __forceinline__ void gfull1(uint32_t ab, uint32_t bb, float* acc,
                                       int m0, int cb, int noff, int khalf) {
    const int rr = noff & 7;
    const uint32_t ar0 = (uint32_t)((m0 + noff) * 256), ar1 = ar0 + 4096;
    const uint32_t br0 = (uint32_t)((cb + noff) * 256), br1 = br0 + 4096;
#pragma unroll
    for (int j = 0; j < 8; j++)
        gchunk1(ab, bb, acc, ar0, ar1, br0, br1, SWC(2 * j + khalf, rr));
}
__device__ __forceinline__ void gvar1(uint32_t ab, uint32_t bb, float* acc,
                                      int m0, int cb, int noff, int khalf, int jmax) {
    const int rr = noff & 7;
    const uint32_t ar0 = (uint32_t)((m0 + noff) * 256), ar1 = ar0 + 4096;
    const uint32_t br0 = (uint32_t)((cb + noff) * 256), br1 = br0 + 4096;
#pragma unroll 2
    for (int j = 0; j < jmax; j++)
        gchunk1(ab, bb, acc, ar0, ar1, br0, br1, SWC(2 * j + khalf, rr));
}

__device__ __forceinline__ void zacc(float* acc) {
#pragma unroll
    for (int i = 0; i < 32; i++) acc[i] = 0.0f;
}

// store acc as hi/lo fp16 image
__device__ __forceinline__ void simg(uint32_t ibase, const float* acc, int m0, int cb,
                                     int g, int q) {
#pragma unroll
    for (int rs = 0; rs < 2; rs++)
#pragma unroll
        for (int tn = 0; tn < 2; tn++) {
            const float* e = acc + rs * 16 + tn * 8;
            int row = m0 + 16 * rs + g;
            uint32_t a0 = ibase + (uint32_t)(row * 256) + SWC((cb >> 3) + 2 * tn, g) + 4 * q;
            uint32_t a1 = ibase + (uint32_t)(row * 256) + SWC((cb >> 3) + 2 * tn + 1, g) + 4 * q;
            uint32_t h0 = f2h2(e[0], e[1]), h1 = f2h2(e[2], e[3]);
            float2 f0 = h2f2(h0), f1 = h2f2(h1);
            uint32_t l0 = f2h2(e[0] - f0.x, e[1] - f0.y);
            uint32_t l1 = f2h2(e[2] - f1.x, e[3] - f1.y);
            STS32(a0, h0);        STS32(a0 + 32768, l0);
            STS32(a0 + 2048, h1); STS32(a0 + 2048 + 32768, l1);
            uint32_t h2 = f2h2(e[4], e[5]), h3 = f2h2(e[6], e[7]);
            float2 f2 = h2f2(h2), f3 = h2f2(h3);
            uint32_t l2 = f2h2(e[4] - f2.x, e[5] - f2.y);
            uint32_t l3 = f2h2(e[6] - f3.x, e[7] - f3.y);
            STS32(a1, h2);        STS32(a1 + 32768, l2);
            STS32(a1 + 2048, h3); STS32(a1 + 2048 + 32768, l3);
        }
}
// store acc as hi-only fp16 image
__device__ __forceinline__ void simgh(uint32_t ibase, const float* acc, int m0, int cb,
                                      int g, int q) {
#pragma unroll
    for (int rs = 0; rs < 2; rs++)
#pragma unroll
        for (int tn = 0; tn < 2; tn++) {
            const float* e = acc + rs * 16 + tn * 8;
            int row = m0 + 16 * rs + g;
            uint32_t a0 = ibase + (uint32_t)(row * 256) + SWC((cb >> 3) + 2 * tn, g) + 4 * q;
            uint32_t a1 = ibase + (uint32_t)(row * 256) + SWC((cb >> 3) + 2 * tn + 1, g) + 4 * q;
            STS32(a0, f2h2(e[0], e[1]));
            STS32(a0 + 2048, f2h2(e[2], e[3]));
            STS32(a1, f2h2(e[4], e[5]));
            STS32(a1 + 2048, f2h2(e[6], e[7]));
        }
}

__device__ __forceinline__ void biasc(float* acc, const float* __restrict__ bias,
                                      int cb, int q) {
#pragma unroll
    for (int rs = 0; rs < 2; rs++)
#pragma unroll
        for (int tn = 0; tn < 2; tn++) {
            float* e = acc + rs * 16 + tn * 8;
            float2 b0 = __ldg((const float2*)(bias + cb + 16 * tn + 2 * q));
            float2 b1 = __ldg((const float2*)(bias + cb + 16 * tn + 8 + 2 * q));
            e[0] += b0.x; e[1] += b0.y; e[2] += b0.x; e[3] += b0.y;
            e[4] += b1.x; e[5] += b1.y; e[6] += b1.x; e[7] += b1.y;
        }
}

// ============ main kernel ============
__global__ void __launch_bounds__(THREADS, 1)
fused_hmmaC(const float* __restrict__ x, const float* __restrict__ te,
            const float* __restrict__ bq, const float* __restrict__ bk,
            const float* __restrict__ bv, const float* __restrict__ bo,
            const float* __restrict__ b1, const float* __restrict__ b2,
            float* __restrict__ out) {
    extern __shared__ char smc[];
    const uint32_t sb = smem_u32(smc);
    const uint32_t B0 = sb + BUF0, B1 = sb + BUF1, B2 = sb + BUF2, W = sb + WOFF;
    const uint32_t SCA = sb + SCOFF;
    const uint32_t WS = W;                // LN sumsq scratch (V^T dead by LN time)

    const int tid = threadIdx.x, lane = tid & 31, w = tid >> 5;
    const int wm = w >> 2, wn = w & 3;
    const int m0 = 32 * wm, cb = 32 * wn;
    const int g = lane >> 2, q = lane & 3;
    const int noff = ((lane >> 3) & 1) * 8 + (lane & 7);
    const int khalf = lane >> 4;
    const int rA = m0 + g;

    const int bn = blockIdx.x, b = bn >> 8, n = bn & 255;
    const float* xb  = x  + (size_t)b * 128 * TSTRIDE + (size_t)n * 128;
    const float* teb = te + (size_t)b * 128 * TSTRIDE + (size_t)n * 128;
    float* ob = out + (size_t)b * 128 * TSTRIDE + (size_t)n * 128;

    // G0: Wk -> B2, Wq -> B1 (both h+l)
    cpa64(B2, g_w[0], tid);
    cpa64(B1, g_w[1], tid);
    CP_COMMIT;

    // ---- build X = x+te hi/lo fp16 image -> BUF0 ----
    {
        int row = tid >> 2, quarter = tid & 3;
        const float4* xr = (const float4*)(xb  + (size_t)row * TSTRIDE + 32 * quarter);
        const float4* tr = (const float4*)(teb + (size_t)row * TSTRIDE + 32 * quarter);
#pragma unroll
        for (int ci = 0; ci < 4; ci++) {
            float4 a = xr[2*ci], c = tr[2*ci], a2 = xr[2*ci+1], c2 = tr[2*ci+1];
            float v0 = a.x + c.x, v1 = a.y + c.y, v2 = a.z + c.z, v3 = a.w + c.w;
            float v4 = a2.x + c2.x, v5 = a2.y + c2.y, v6 = a2.z + c2.z, v7 = a2.w + c2.w;
            uint32_t h0 = f2h2(v0, v1), h1 = f2h2(v2, v3);
            uint32_t h2 = f2h2(v4, v5), h3 = f2h2(v6, v7);
            float2 e0 = h2f2(h0), e1 = h2f2(h1), e2 = h2f2(h2), e3 = h2f2(h3);
            uint32_t l0 = f2h2(v0 - e0.x, v1 - e0.y), l1 = f2h2(v2 - e1.x, v3 - e1.y);
            uint32_t l2 = f2h2(v4 - e2.x, v5 - e2.y), l3 = f2h2(v6 - e3.x, v7 - e3.y);
            uint32_t addr = B0 + (uint32_t)row * 256 + SWC(4 * quarter + ci, row & 7);
            STS128(addr, h0, h1, h2, h3);
            STS128(addr + 32768, l0, l1, l2, l3);
        }
    }
    CP_WAITALL;
    __syncthreads();

    float acc[32];

    // ==== P1: K = X @ Wk (3-pass) -> B2 ====
    zacc(acc);
    gfull(B0, B0 + 32768, B2, B2 + 32768, acc, m0, cb, noff, khalf);
    biasc(acc, bk, cb, q);
    __syncthreads();
    simg(B2, acc, m0, cb, g, q);

    // ==== P2: Q = X @ Wq (3-pass, Wq in B1) -> B1 ====
    zacc(acc);
    gfull(B0, B0 + 32768, B1, B1 + 32768, acc, m0, cb, noff, khalf);
    biasc(acc, bq, cb, q);
    __syncthreads();                       // Wq + X-lo reads done
    cpa32(W, g_w[2], tid);                 // Wv-hi -> W
    cpa32(B0 + 32768, g_w[2] + 32768, tid);// Wv-lo -> X-lo region (X-lo dead)
    CP_COMMIT;
    simg(B1, acc, m0, cb, g, q);           // Q image (over Wq)
    CP_WAITALL;
    __syncthreads();

    // ==== P3: V^T = Wv @ Xh (2-pass) -> W (hi-only) ====
    zacc(acc);
    gfull2(W, B0 + 32768, B0, acc, m0, cb, noff, khalf);
    {
        float bv0 = __ldg(bv + rA), bv1 = __ldg(bv + rA + 8);
        float bv2 = __ldg(bv + rA + 16), bv3 = __ldg(bv + rA + 24);
#pragma unroll
        for (int tn = 0; tn < 2; tn++) {
#pragma unroll
            for (int j = 0; j < 4; j++) {
                acc[8*tn + j] += (j < 2) ? bv0 : bv1;
                acc[8*tn + 4 + j] += (j < 2) ? bv0 : bv1;
                acc[16 + 8*tn + j] += (j < 2) ? bv2 : bv3;
                acc[16 + 8*tn + 4 + j] += (j < 2) ? bv2 : bv3;
            }
        }
    }
    __syncthreads();                       // Wv + X reads done
    simgh(W, acc, m0, cb, g, q);           // V^T hi-only image

    // ==== P4: S (assigned tile, 3-pass) -> softmax -> P (hi-only) -> B0 ====
    {
        const int sm = (int)((SMTAB >> (4 * w)) & 7);
        const int sn = (int)((SNTAB >> (4 * w)) & 7);
        const bool masked = sn > sm;
        const int sm0 = 32 * sm, scb = 32 * sn;
        const int rS = sm0 + g;
        zacc(acc);
        if (!masked)
            gfull(B1, B1 + 32768, B2, B2 + 32768, acc, sm0, scb, noff, khalf);
        float s[4] = {0, 0, 0, 0};
        if (!masked) {
#pragma unroll
            for (int rs = 0; rs < 2; rs++)
#pragma unroll
                for (int tn = 0; tn < 2; tn++) {
                    float* e = acc + rs * 16 + tn * 8;
                    int ra = rS + 16 * rs, rb = ra + 8;
                    int c0 = scb + 16 * tn + 2 * q;
                    int c1 = c0 + 8;
                    float p0 = (c0     <= ra) ? __expf(e[0] * 0.25f) : 0.0f;
                    float p1 = (c0 + 1 <= ra) ? __expf(e[1] * 0.25f) : 0.0f;
                    float p2 = (c0     <= rb) ? __expf(e[2] * 0.25f) : 0.0f;
                    float p3 = (c0 + 1 <= rb) ? __expf(e[3] * 0.25f) : 0.0f;
                    float p4 = (c1     <= ra) ? __expf(e[4] * 0.25f) : 0.0f;
                    float p5 = (c1 + 1 <= ra) ? __expf(e[5] * 0.25f) : 0.0f;
                    float p6 = (c1     <= rb) ? __expf(e[6] * 0.25f) : 0.0f;
                    float p7 = (c1 + 1 <= rb) ? __expf(e[7] * 0.25f) : 0.0f;
                    e[0]=p0; e[1]=p1; e[2]=p2; e[3]=p3; e[4]=p4; e[5]=p5; e[6]=p6; e[7]=p7;
                    s[2*rs]   += p0 + p1 + p4 + p5;
                    s[2*rs+1] += p2 + p3 + p6 + p7;
                }
        }
        QRED(s[0]); QRED(s[1]); QRED(s[2]); QRED(s[3]);
        STSF(SCA + (uint32_t)(4 * rS + sn) * 4, s[0]);
        STSF(SCA + (uint32_t)(4 * (rS + 8) + sn) * 4, s[1]);
        STSF(SCA + (uint32_t)(4 * (rS + 16) + sn) * 4, s[2]);
        STSF(SCA + (uint32_t)(4 * (rS + 24) + sn) * 4, s[3]);
        __syncthreads();                   // K,Q reads + sums done
        cpa32(B2, g_w[3], tid); CP_COMMIT; // Wo-hi -> B2 (K dead)
        if (!masked) {
            float inv[4];
#pragma unroll
            for (int i = 0; i < 4; i++) {
                float a0, a1, a2, a3;
                uint32_t base = SCA + (uint32_t)(4 * (rS + 8 * i)) * 4;
                LDSF(a0, base); LDSF(a1, base + 4); LDSF(a2, base + 8); LDSF(a3, base + 12);
                inv[i] = 1.0f / (a0 + a1 + a2 + a3);
            }
#pragma unroll
            for (int rs = 0; rs < 2; rs++)
#pragma unroll
                for (int tn = 0; tn < 2; tn++) {
                    float* e = acc + rs * 16 + tn * 8;
                    e[0] *= inv[2*rs]; e[1] *= inv[2*rs];
                    e[2] *= inv[2*rs+1]; e[3] *= inv[2*rs+1];
                    e[4] *= inv[2*rs]; e[5] *= inv[2*rs];
                    e[6] *= inv[2*rs+1]; e[7] *= inv[2*rs+1];
                }
            simgh(B0, acc, sm0, scb, g, q);// P hi-only image (X dead)
        }
        __syncthreads();
    }

    // ==== P5: AO = P @ V (1-pass; jmax = 2wm+2) -> B1 (h+l) ====
    zacc(acc);
    gvar1(B0, W, acc, m0, cb, noff, khalf, 2 * wm + 2);
    __syncthreads();                       // P + V reads done
    simg(B1, acc, m0, cb, g, q);           // AO image (Q dead)
    CP_WAITALL;
    __syncthreads();                       // AO + Wo visible

    // ==== P6: U = LN(AO @ Wo + bo + (x+te)) (2-pass) -> B0 (h+l) ====
    zacc(acc);
    gfull2(B1, B1 + 32768, B2, acc, m0, cb, noff, khalf);
    biasc(acc, bo, cb, q);
#pragma unroll
    for (int rs = 0; rs < 2; rs++)
#pragma unroll
        for (int tn = 0; tn < 2; tn++) {
            float* e = acc + rs * 16 + tn * 8;
            int c = cb + 16 * tn + 2 * q;
            size_t ra = (size_t)(rA + 16 * rs), rb = ra + 8;
            float2 xa = *(const float2*)(xb + ra * TSTRIDE + c);
            float2 ta = *(const float2*)(teb + ra * TSTRIDE + c);
            e[0] += xa.x + ta.x; e[1] += xa.y + ta.y;
            float2 xc = *(const float2*)(xb + rb * TSTRIDE + c);
            float2 tc = *(const float2*)(teb + rb * TSTRIDE + c);
            e[2] += xc.x + tc.x; e[3] += xc.y + tc.y;
            float2 xe = *(const float2*)(xb + ra * TSTRIDE + c + 8);
            float2 tee = *(const float2*)(teb + ra * TSTRIDE + c + 8);
            e[4] += xe.x + tee.x; e[5] += xe.y + tee.y;
            float2 xg = *(const float2*)(xb + rb * TSTRIDE + c + 8);
            float2 tg = *(const float2*)(teb + rb * TSTRIDE + c + 8);
            e[6] += xg.x + tg.x; e[7] += xg.y + tg.y;
        }
    {   // 1-round LN
        float s[4] = {0,0,0,0}, qq[4] = {0,0,0,0};
#pragma unroll
        for (int rs = 0; rs < 2; rs++)
#pragma unroll
            for (int tn = 0; tn < 2; tn++) {
                float* e = acc + rs * 16 + tn * 8;
                s[2*rs]   += e[0] + e[1] + e[4] + e[5];
                s[2*rs+1] += e[2] + e[3] + e[6] + e[7];
                qq[2*rs]   += e[0]*e[0] + e[1]*e[1] + e[4]*e[4] + e[5]*e[5];
                qq[2*rs+1] += e[2]*e[2] + e[3]*e[3] + e[6]*e[6] + e[7]*e[7];
            }
        QRED(s[0]); QRED(s[1]); QRED(s[2]); QRED(s[3]);
        QRED(qq[0]); QRED(qq[1]); QRED(qq[2]); QRED(qq[3]);
#pragma unroll
        for (int i = 0; i < 4; i++) {
            STSF(SCA + (uint32_t)(4 * (rA + 8 * i) + wn) * 4, s[i]);
            STSF(WS + (uint32_t)(4 * (rA + 8 * i) + wn) * 4, qq[i]);
        }
        __syncthreads();                   // also retires Wo + V reads
        float mu[4], iv[4];
#pragma unroll
        for (int i = 0; i < 4; i++) {
            float a0, a1, a2, a3, c0, c1, c2, c3;
            uint32_t bs = SCA + (uint32_t)(4 * (rA + 8 * i)) * 4;
            uint32_t bw = WS + (uint32_t)(4 * (rA + 8 * i)) * 4;
            LDSF(a0, bs); LDSF(a1, bs + 4); LDSF(a2, bs + 8); LDSF(a3, bs + 12);
            LDSF(c0, bw); LDSF(c1, bw + 4); LDSF(c2, bw + 8); LDSF(c3, bw + 12);
            mu[i] = (a0 + a1 + a2 + a3) * 0.0078125f;
            float var = (c0 + c1 + c2 + c3) * 0.0078125f - mu[i] * mu[i];
            iv[i] = rsqrtf(var + 1e-5f);
        }
#pragma unroll
        for (int rs = 0; rs < 2; rs++)
#pragma unroll
            for (int tn = 0; tn < 2; tn++) {
                float* e = acc + rs * 16 + tn * 8;
                e[0] = (e[0] - mu[2*rs]) * iv[2*rs];   e[1] = (e[1] - mu[2*rs]) * iv[2*rs];
                e[4] = (e[4] - mu[2*rs]) * iv[2*rs];   e[5] = (e[5] - mu[2*rs]) * iv[2*rs];
                e[2] = (e[2] - mu[2*rs+1]) * iv[2*rs+1]; e[3] = (e[3] - mu[2*rs+1]) * iv[2*rs+1];
                e[6] = (e[6] - mu[2*rs+1]) * iv[2*rs+1]; e[7] = (e[7] - mu[2*rs+1]) * iv[2*rs+1];
            }
    }
    cpa32(B2, g_w[4], tid); CP_COMMIT;     // W1 -> B2 (Wo dead)
    simg(B0, acc, m0, cb, g, q);           // U image h+l (P dead)
    CP_WAITALL;
    __syncthreads();

    // ==== P7: H = relu(U @ W1 + b1) (2-pass) -> B1 (hi-only) ====
    zacc(acc);
    gfull2(B0, B0 + 32768, B2, acc, m0, cb, noff, khalf);
    biasc(acc, b1, cb, q);
#pragma unroll
    for (int i = 0; i < 32; i++) acc[i] = fmaxf(acc[i], 0.0f);
    __syncthreads();                       // W1 reads done
    cpa32(B2, g_w[5], tid); CP_COMMIT;     // W2 -> B2
    simgh(B1, acc, m0, cb, g, q);          // H hi-only image (AO dead)
    CP_WAITALL;
    __syncthreads();

    // ==== P8: out = LN(H @ W2 + b2 + U) (1-pass) -> gmem ====
    zacc(acc);
    gfull1(B1, B2, acc, m0, cb, noff, khalf);
    biasc(acc, b2, cb, q);
#pragma unroll
    for (int rs = 0; rs < 2; rs++)
#pragma unroll
        for (int tn = 0; tn < 2; tn++) {   // + U residual from B0 (h+l)
            float* e = acc + rs * 16 + tn * 8;
            int row = m0 + 16 * rs + g;
            uint32_t a0 = B0 + (uint32_t)(row * 256) + SWC((cb >> 3) + 2 * tn, g) + 4 * q;
            uint32_t a1 = B0 + (uint32_t)(row * 256) + SWC((cb >> 3) + 2 * tn + 1, g) + 4 * q;
            uint32_t h, l;
            LDS32(h, a0); LDS32(l, a0 + 32768);
            float2 hf = h2f2(h), lf = h2f2(l);
            e[0] += hf.x + lf.x; e[1] += hf.y + lf.y;
            LDS32(h, a0 + 2048); LDS32(l, a0 + 2048 + 32768);
            hf = h2f2(h); lf = h2f2(l);
            e[2] += hf.x + lf.x; e[3] += hf.y + lf.y;
            LDS32(h, a1); LDS32(l, a1 + 32768);
            hf = h2f2(h); lf = h2f2(l);
            e[4] += hf.x + lf.x; e[5] += hf.y + lf.y;
            LDS32(h, a1 + 2048); LDS32(l, a1 + 2048 + 32768);
            hf = h2f2(h); lf = h2f2(l);
            e[6] += hf.x + lf.x; e[7] += hf.y + lf.y;
        }
    {   // 1-round final LN
        float s[4] = {0,0,0,0}, qq[4] = {0,0,0,0};
#pragma unroll
        for (int rs = 0; rs < 2; rs++)
#pragma unroll
            for (int tn = 0; tn < 2; tn++) {
                float* e = acc + rs * 16 + tn * 8;
                s[2*rs]   += e[0] + e[1] + e[4] + e[5];
                s[2*rs+1] += e[2] + e[3] + e[6] + e[7];
                qq[2*rs]   += e[0]*e[0] + e[1]*e[1] + e[4]*e[4] + e[5]*e[5];
                qq[2*rs+1] += e[2]*e[2] + e[3]*e[3] + e[6]*e[6] + e[7]*e[7];
            }
        QRED(s[0]); QRED(s[1]); QRED(s[2]); QRED(s[3]);
        QRED(qq[0]); QRED(qq[1]); QRED(qq[2]); QRED(qq[3]);
#pragma unroll
        for (int i = 0; i < 4; i++) {
            STSF(SCA + (uint32_t)(4 * (rA + 8 * i) + wn) * 4, s[i]);
            STSF(WS + (uint32_t)(4 * (rA + 8 * i) + wn) * 4, qq[i]);
        }
        __syncthreads();
        float mu[4], iv[4];
#pragma unroll
        for (int i = 0; i < 4; i++) {
            float a0, a1, a2, a3, c0, c1, c2, c3;
            uint32_t bs = SCA + (uint32_t)(4 * (rA + 8 * i)) * 4;
            uint32_t bw = WS + (uint32_t)(4 * (rA + 8 * i)) * 4;
            LDSF(a0, bs); LDSF(a1, bs + 4); LDSF(a2, bs + 8); LDSF(a3, bs + 12);
            LDSF(c0, bw); LDSF(c1, bw + 4); LDSF(c2, bw + 8); LDSF(c3, bw + 12);
            mu[i] = (a0 + a1 + a2 + a3) * 0.0078125f;
            float var = (c0 + c1 + c2 + c3) * 0.0078125f - mu[i] * mu[i];
            iv[i] = rsqrtf(var + 1e-5f);
        }
#pragma unroll
        for (int rs = 0; rs < 2; rs++)
#pragma unroll
            for (int tn = 0; tn < 2; tn++) {
                float* e = acc + rs * 16 + tn * 8;
                int c = cb + 16 * tn + 2 * q;
                size_t ra = (size_t)(rA + 16 * rs), rb = ra + 8;
                *(float2*)(ob + ra * TSTRIDE + c) =
                    make_float2((e[0] - mu[2*rs]) * iv[2*rs], (e[1] - mu[2*rs]) * iv[2*rs]);
                *(float2*)(ob + rb * TSTRIDE + c) =
                    make_float2((e[2] - mu[2*rs+1]) * iv[2*rs+1], (e[3] - mu[2*rs+1]) * iv[2*rs+1]);
                *(float2*)(ob + ra * TSTRIDE + c + 8) =
                    make_float2((e[4] - mu[2*rs]) * iv[2*rs], (e[5] - mu[2*rs]) * iv[2*rs]);
                *(float2*)(ob + rb * TSTRIDE + c + 8) =
                    make_float2((e[6] - mu[2*rs+1]) * iv[2*rs+1], (e[7] - mu[2*rs+1]) * iv[2*rs+1]);
            }
    }
}

extern "C" void kernel_launch(void* const* d_in, const int* in_sizes, int n_in,
                              void* d_out, int out_size) {
    const float* x  = (const float*)d_in[0];
    const float* te = (const float*)d_in[1];
    const float* wq = (const float*)d_in[2];
    const float* bq = (const float*)d_in[3];
    const float* wk = (const float*)d_in[4];
    const float* bk = (const float*)d_in[5];
    const float* wv = (const float*)d_in[6];
    const float* bv = (const float*)d_in[7];
    const float* wo = (const float*)d_in[8];
    const float* bo = (const float*)d_in[9];
    const float* w1 = (const float*)d_in[10];
    const float* b1 = (const float*)d_in[11];
    const float* w2 = (const float*)d_in[12];
    const float* b2 = (const float*)d_in[13];
    float* out = (float*)d_out;

    prep_w<<<6, 256>>>(wk, wq, wv, wo, w1, w2);
    cudaFuncSetAttribute(fused_hmmaC, cudaFuncAttributeMaxDynamicSharedMemorySize, SMEM_TOT);
    fused_hmmaC<<<4096, THREADS, SMEM_TOT>>>(x, te, bq, bk, bv, bo, b1, b2, out);
}